// round 13
// baseline (speedup 1.0000x reference)
#include <cuda_runtime.h>
#include <cuda_bf16.h>
#include <math.h>
#include <stdint.h>

// Problem constants
#define NN    10000
#define EE    160000
#define EP    170000
#define HH    8
#define CC    64
#define HC    512
#define GG    64
#define NCLS  64
#define NBN   400            // bn partial blocks (25 rows each)

// ---------------- device scratch ----------------
__device__ float g_bufA[NN * HC];
__device__ float g_bufB[NN * HC];
__device__ float g_h[NN * HC];
__device__ float g_gat[NN * HC];
__device__ float g_ssrc[NN * HH];
__device__ float g_sdst[NN * HH];
__device__ float g_x3[NN * CC];
__device__ float g_gat3[NN * CC];
__device__ int   g_rowptr[NN + 1];
__device__ int   g_cnt[NN];
__device__ int   g_csrc[EP];
__device__ float g_bnpart[NBN * HC];
__device__ float g_bnpart2[NBN * HC];
__device__ int   g_bncnt;
__device__ float g_scale[HC];
__device__ float g_shift[HC];
__device__ __nv_bfloat16 g_Ah[NN * HC];
__device__ __nv_bfloat16 g_Al[NN * HC];
__device__ __nv_bfloat16 g_Ah2[NN * HC];
__device__ __nv_bfloat16 g_Al2[NN * HC];
__device__ __nv_bfloat16 g_WthA[4][HC * HC];
__device__ __nv_bfloat16 g_WtlA[4][HC * HC];

// ======================= helpers =======================
__device__ __forceinline__ uint32_t smem_to_u32(const void* p) {
    uint32_t a;
    asm("{ .reg .u64 t; cvta.to.shared.u64 t, %1; cvt.u32.u64 %0, t; }" : "=r"(a) : "l"(p));
    return a;
}
__device__ __forceinline__ void ldm_x4(uint32_t* r, uint32_t addr) {
    asm volatile("ldmatrix.sync.aligned.m8n8.x4.shared.b16 {%0,%1,%2,%3}, [%4];"
                 : "=r"(r[0]), "=r"(r[1]), "=r"(r[2]), "=r"(r[3]) : "r"(addr));
}
__device__ __forceinline__ void mma16816(float* c, const uint32_t* a, const uint32_t* b) {
    asm volatile(
        "mma.sync.aligned.m16n8k16.row.col.f32.bf16.bf16.f32 "
        "{%0,%1,%2,%3}, {%4,%5,%6,%7}, {%8,%9}, {%0,%1,%2,%3};"
        : "+f"(c[0]), "+f"(c[1]), "+f"(c[2]), "+f"(c[3])
        : "r"(a[0]), "r"(a[1]), "r"(a[2]), "r"(a[3]), "r"(b[0]), "r"(b[1]));
}
__device__ __forceinline__ void cp16(uint32_t dst, const void* src, int sz) {
    asm volatile("cp.async.cg.shared.global [%0], [%1], 16, %2;"
                 :: "r"(dst), "l"(src), "r"(sz));
}
#define CP_COMMIT() asm volatile("cp.async.commit_group;" ::: "memory")
#define CP_WAIT(n)  asm volatile("cp.async.wait_group %0;" :: "n"(n) : "memory")

__device__ __forceinline__ void split_bf16(float v, __nv_bfloat16& h, __nv_bfloat16& l) {
    h = __float2bfloat16(v);
    l = __float2bfloat16(v - __bfloat162float(h));
}

// ======================= prep mega-kernel =======================
__global__ void k_prep(const float* __restrict__ x,
                       __nv_bfloat16* __restrict__ Ah, __nv_bfloat16* __restrict__ Al,
                       const float* __restrict__ W0, const float* __restrict__ W1,
                       const float* __restrict__ W2, const float* __restrict__ W3) {
    int z = blockIdx.z;
    int tx = threadIdx.x, ty = threadIdx.y;
    int tid = ty * 32 + tx;
    if (z < 4) {
        const float* W = (z == 0) ? W0 : (z == 1) ? W1 : (z == 2) ? W2 : W3;
        int Nn = (z == 3) ? CC : HC;
        int bx = blockIdx.x * 32;
        int by = blockIdx.y * 32;
        if (bx >= Nn) return;
        __shared__ float t[32][33];
#pragma unroll
        for (int j = 0; j < 32; j += 8)
            t[ty + j][tx] = W[(size_t)(by + ty + j) * Nn + bx + tx];
        __syncthreads();
        __nv_bfloat16* th = g_WthA[z];
        __nv_bfloat16* tl = g_WtlA[z];
#pragma unroll
        for (int j = 0; j < 32; j += 8) {
            float v = t[tx][ty + j];
            __nv_bfloat16 h, l;
            split_bf16(v, h, l);
            size_t o = (size_t)(bx + ty + j) * HC + by + tx;
            th[o] = h; tl[o] = l;
        }
    } else if (z == 4) {
        int i = (blockIdx.y * 16 + blockIdx.x) * 256 + tid;
        if (i == 0) g_bncnt = 0;
        if (i < NN) g_cnt[i] = 0;
        for (int s = i; s < NN * HH; s += 65536) { g_ssrc[s] = 0.f; g_sdst[s] = 0.f; }
    } else {
        const int n4 = NN * HC / 4;
        int i = (blockIdx.y * 16 + blockIdx.x) * 256 + tid;
        for (; i < n4; i += 65536) {
            float4 v = ((const float4*)x)[i];
            __nv_bfloat16 h0, h1, h2, h3, l0, l1, l2, l3;
            split_bf16(v.x, h0, l0); split_bf16(v.y, h1, l1);
            split_bf16(v.z, h2, l2); split_bf16(v.w, h3, l3);
            ((__nv_bfloat162*)Ah)[2 * i]     = __halves2bfloat162(h0, h1);
            ((__nv_bfloat162*)Ah)[2 * i + 1] = __halves2bfloat162(h2, h3);
            ((__nv_bfloat162*)Al)[2 * i]     = __halves2bfloat162(l0, l1);
            ((__nv_bfloat162*)Al)[2 * i + 1] = __halves2bfloat162(l2, l3);
        }
    }
}

// ======================= cp.async double-buffered warp-MMA GEMM =======================
// BN=64 fixed: BM=128, BK=64, 256 threads = 8 warps (4M x 2N), warp tile 32x32,
// 2 CTAs/SM (regs ~119). Proven config (R11).
#define AH_OFF 0
#define AL_OFF 16384
#define BH_OFF 32768
#define BL_OFF 40960
#define STG    49152
#define SMEM_GEMM (2 * STG)

__global__ __launch_bounds__(256, 2)
void k_gemm_mma(const __nv_bfloat16* __restrict__ Ah, const __nv_bfloat16* __restrict__ Al,
                const __nv_bfloat16* __restrict__ Bh, const __nv_bfloat16* __restrict__ Bl,
                const float* __restrict__ bias, float* __restrict__ Cm,
                __nv_bfloat16* __restrict__ outH, __nv_bfloat16* __restrict__ outL,
                const float* __restrict__ aS, const float* __restrict__ aD, int Hh,
                int M, int Nn) {
    extern __shared__ char smem[];
    const uint32_t sb = smem_to_u32(smem);
    const int tid = threadIdx.x;
    const int lane = tid & 31;
    const int wid = tid >> 5;
    const int warpM = wid & 3;
    const int warpN = wid >> 2;
    const int bm = blockIdx.y * 128;
    const int bn = blockIdx.x * 64;

    float acc[2][4][4];
#pragma unroll
    for (int mt = 0; mt < 2; mt++)
#pragma unroll
        for (int nt = 0; nt < 4; nt++)
#pragma unroll
            for (int r = 0; r < 4; r++) acc[mt][nt][r] = 0.f;

    auto issue = [&](int kb, int buf) {
        const uint32_t sbase = sb + buf * STG;
#pragma unroll
        for (int it = 0; it < 4; it++) {
            int idx = tid + it * 256;
            int r = idx >> 3, c16 = idx & 7;
            uint32_t so = (uint32_t)(r * 128 + c16 * 16);
            so ^= (so >> 3) & 0x70;
            int gr = bm + r;
            int grc = gr < M ? gr : 0;
            int sz = gr < M ? 16 : 0;
            size_t goff = (size_t)grc * 512 + kb * 64 + c16 * 8;
            cp16(sbase + AH_OFF + so, Ah + goff, sz);
            cp16(sbase + AL_OFF + so, Al + goff, sz);
        }
#pragma unroll
        for (int it = 0; it < 2; it++) {
            int idx = tid + it * 256;
            int r = idx >> 3, c16 = idx & 7;
            uint32_t so = (uint32_t)(r * 128 + c16 * 16);
            so ^= (so >> 3) & 0x70;
            size_t goff = (size_t)(bn + r) * 512 + kb * 64 + c16 * 8;
            cp16(sbase + BH_OFF + so, Bh + goff, 16);
            cp16(sbase + BL_OFF + so, Bl + goff, 16);
        }
    };

    const uint32_t aRow = (uint32_t)(warpM * 32 + (lane & 15));
    const uint32_t aC16b = (uint32_t)(lane >> 4);
    const uint32_t bRow = (uint32_t)(warpN * 32 + ((lane >> 4) << 3) + (lane & 7));
    const uint32_t bC16b = (uint32_t)((lane >> 3) & 1);

    issue(0, 0);
    CP_COMMIT();

    for (int kb = 0; kb < 8; kb++) {
        if (kb + 1 < 8) { issue(kb + 1, (kb + 1) & 1); CP_COMMIT(); }
        if (kb + 1 < 8) { CP_WAIT(1); } else { CP_WAIT(0); }
        __syncthreads();
        const uint32_t sbase = sb + (kb & 1) * STG;
#pragma unroll
        for (int ks = 0; ks < 4; ks++) {
            uint32_t ah[2][4], al[2][4], bh[2][4], bl[2][4];
            uint32_t ac16 = (uint32_t)(ks * 2) + aC16b;
            uint32_t bc16 = (uint32_t)(ks * 2) + bC16b;
#pragma unroll
            for (int mt = 0; mt < 2; mt++) {
                uint32_t off = (aRow + mt * 16) * 128 + ac16 * 16;
                off ^= (off >> 3) & 0x70;
                ldm_x4(ah[mt], sbase + AH_OFF + off);
            }
#pragma unroll
            for (int half = 0; half < 2; half++) {
                uint32_t off = (bRow + half * 16) * 128 + bc16 * 16;
                off ^= (off >> 3) & 0x70;
                ldm_x4(bh[half], sbase + BH_OFF + off);
            }
#pragma unroll
            for (int mt = 0; mt < 2; mt++) {
                uint32_t off = (aRow + mt * 16) * 128 + ac16 * 16;
                off ^= (off >> 3) & 0x70;
                ldm_x4(al[mt], sbase + AL_OFF + off);
            }
#pragma unroll
            for (int half = 0; half < 2; half++) {
                uint32_t off = (bRow + half * 16) * 128 + bc16 * 16;
                off ^= (off >> 3) & 0x70;
                ldm_x4(bl[half], sbase + BL_OFF + off);
            }
#pragma unroll
            for (int mt = 0; mt < 2; mt++)
#pragma unroll
                for (int nt = 0; nt < 4; nt++)
                    mma16816(acc[mt][nt], ah[mt], &bh[nt >> 1][(nt & 1) * 2]);
#pragma unroll
            for (int mt = 0; mt < 2; mt++)
#pragma unroll
                for (int nt = 0; nt < 4; nt++)
                    mma16816(acc[mt][nt], al[mt], &bh[nt >> 1][(nt & 1) * 2]);
#pragma unroll
            for (int mt = 0; mt < 2; mt++)
#pragma unroll
                for (int nt = 0; nt < 4; nt++)
                    mma16816(acc[mt][nt], ah[mt], &bl[nt >> 1][(nt & 1) * 2]);
        }
        __syncthreads();
    }

    const int rowBase = bm + warpM * 32 + (lane >> 2);
    const int colBase = bn + warpN * 32 + (lane & 3) * 2;
#pragma unroll
    for (int mt = 0; mt < 2; mt++) {
#pragma unroll
        for (int nt = 0; nt < 4; nt++) {
            int gc = colBase + nt * 8;
            float b0 = 0.f, b1 = 0.f;
            if (bias) { b0 = bias[gc]; b1 = bias[gc + 1]; }
#pragma unroll
            for (int half = 0; half < 2; half++) {
                int r = rowBase + mt * 16 + half * 8;
                if (r < M) {
                    float v0 = acc[mt][nt][half * 2] + b0;
                    float v1 = acc[mt][nt][half * 2 + 1] + b1;
                    *(float2*)(Cm + (size_t)r * Nn + gc) = make_float2(v0, v1);
                    if (outH) {
                        __nv_bfloat16 h0, h1, l0, l1;
                        split_bf16(v0, h0, l0);
                        split_bf16(v1, h1, l1);
                        *(__nv_bfloat162*)(outH + (size_t)r * Nn + gc) = __halves2bfloat162(h0, h1);
                        *(__nv_bfloat162*)(outL + (size_t)r * Nn + gc) = __halves2bfloat162(l0, l1);
                    }
                }
            }
        }
    }

    // ---- fused attention score partials (head == blockIdx.x since BN == CC == 64) ----
    if (aS) {
        const int head = blockIdx.x;
        const float* aSh = aS + head * CC;
        const float* aDh = aD + head * CC;
        const int colh0 = warpN * 32 + (lane & 3) * 2;
#pragma unroll
        for (int mt = 0; mt < 2; mt++) {
#pragma unroll
            for (int half = 0; half < 2; half++) {
                float s1 = 0.f, s2 = 0.f;
#pragma unroll
                for (int nt = 0; nt < 4; nt++) {
                    int colh = colh0 + nt * 8;
                    float v0 = acc[mt][nt][half * 2];
                    float v1 = acc[mt][nt][half * 2 + 1];
                    s1 += v0 * aSh[colh] + v1 * aSh[colh + 1];
                    s2 += v0 * aDh[colh] + v1 * aDh[colh + 1];
                }
                s1 += __shfl_xor_sync(0xffffffffu, s1, 1);
                s1 += __shfl_xor_sync(0xffffffffu, s1, 2);
                s2 += __shfl_xor_sync(0xffffffffu, s2, 1);
                s2 += __shfl_xor_sync(0xffffffffu, s2, 2);
                int r = rowBase + mt * 16 + half * 8;
                if ((lane & 3) == 0 && r < M) {
                    atomicAdd(&g_ssrc[r * Hh + head], s1);
                    atomicAdd(&g_sdst[r * Hh + head], s2);
                }
            }
        }
    }
}

// ---------------- CSR build ----------------
__global__ void k_count(const int* __restrict__ ei) {
    int e = blockIdx.x * blockDim.x + threadIdx.x;
    if (e < EE) atomicAdd(&g_cnt[ei[EE + e]], 1);
}
__global__ void k_scanfill() {
    __shared__ int sh[1024];
    __shared__ int carry;
    int tid = threadIdx.x;
    if (tid == 0) carry = 0;
    __syncthreads();
    for (int base = 0; base < NN; base += 1024) {
        int i = base + tid;
        int v = (i < NN) ? (g_cnt[i] + 1) : 0;
        sh[tid] = v;
        __syncthreads();
        for (int off = 1; off < 1024; off <<= 1) {
            int t = (tid >= off) ? sh[tid - off] : 0;
            __syncthreads();
            sh[tid] += t;
            __syncthreads();
        }
        if (i < NN) g_rowptr[i + 1] = carry + sh[tid];
        __syncthreads();
        if (tid == 1023) carry += sh[1023];
        __syncthreads();
    }
    if (tid == 0) g_rowptr[0] = 0;
    __syncthreads();
    for (int i = tid; i < NN; i += 1024) {
        int rp = (i == 0) ? 0 : g_rowptr[i];
        g_csrc[rp] = i;
        g_cnt[i] = rp + 1;
    }
}
__global__ void k_fill(const int* __restrict__ ei) {
    int e = blockIdx.x * blockDim.x + threadIdx.x;
    if (e < EE) {
        int dst = ei[EE + e];
        int slot = atomicAdd(&g_cnt[dst], 1);
        g_csrc[slot] = ei[e];
    }
}

__device__ __forceinline__ float lrelu02(float x) { return x > 0.f ? x : 0.2f * x; }

// ---------------- GAT aggregation, H=8, shared-alpha ----------------
__global__ void k_agg8(const float* __restrict__ hbuf, const float* __restrict__ ssrc,
                       const float* __restrict__ sdst, const float* __restrict__ bias,
                       float* __restrict__ out) {
    int dstn = blockIdx.x;
    int tid = threadIdx.x;
    __shared__ float sh_sdst[HH], sh_m[HH], sh_sinv[HH];
    __shared__ float sh_alpha[32 * HH];
    __shared__ int   sh_src[32];
    if (tid < HH) sh_sdst[tid] = sdst[dstn * HH + tid];
    __syncthreads();
    int beg = g_rowptr[dstn], end = g_rowptr[dstn + 1];
    int warp = tid >> 5, lane = tid & 31;
    {
        int hh = warp * 2 + (lane >> 4);
        int sub = lane & 15;
        float sd = sh_sdst[hh];
        float mx = -3.4e38f;
        for (int i = beg + sub; i < end; i += 16)
            mx = fmaxf(mx, lrelu02(ssrc[g_csrc[i] * HH + hh] + sd));
#pragma unroll
        for (int o = 1; o < 16; o <<= 1) mx = fmaxf(mx, __shfl_xor_sync(0xffffffffu, mx, o));
        float se = 0.f;
        for (int i = beg + sub; i < end; i += 16)
            se += __expf(lrelu02(ssrc[g_csrc[i] * HH + hh] + sd) - mx);
#pragma unroll
        for (int o = 1; o < 16; o <<= 1) se += __shfl_xor_sync(0xffffffffu, se, o);
        if (sub == 0) { sh_m[hh] = mx; sh_sinv[hh] = 1.f / (se + 1e-16f); }
    }
    __syncthreads();
    int hh = tid >> 4;
    int c4 = (tid & 15) << 2;
    float4 acc = make_float4(0.f, 0.f, 0.f, 0.f);
    for (int c0 = beg; c0 < end; c0 += 32) {
        int cnt = min(32, end - c0);
        for (int t = tid; t < cnt * HH; t += 128) {
            int e = t >> 3, h2 = t & 7;
            int s = g_csrc[c0 + e];
            if (h2 == 0) sh_src[e] = s;
            sh_alpha[e * HH + h2] =
                __expf(lrelu02(ssrc[s * HH + h2] + sh_sdst[h2]) - sh_m[h2]) * sh_sinv[h2];
        }
        __syncthreads();
        int e = 0;
        for (; e + 1 < cnt; e += 2) {
            float a0 = sh_alpha[e * HH + hh];
            float a1 = sh_alpha[(e + 1) * HH + hh];
            float4 v0 = *(const float4*)(hbuf + (size_t)sh_src[e] * HC + hh * CC + c4);
            float4 v1 = *(const float4*)(hbuf + (size_t)sh_src[e + 1] * HC + hh * CC + c4);
            acc.x = fmaf(a0, v0.x, fmaf(a1, v1.x, acc.x));
            acc.y = fmaf(a0, v0.y, fmaf(a1, v1.y, acc.y));
            acc.z = fmaf(a0, v0.z, fmaf(a1, v1.z, acc.z));
            acc.w = fmaf(a0, v0.w, fmaf(a1, v1.w, acc.w));
        }
        if (e < cnt) {
            float a0 = sh_alpha[e * HH + hh];
            float4 v0 = *(const float4*)(hbuf + (size_t)sh_src[e] * HC + hh * CC + c4);
            acc.x = fmaf(a0, v0.x, acc.x);
            acc.y = fmaf(a0, v0.y, acc.y);
            acc.z = fmaf(a0, v0.z, acc.z);
            acc.w = fmaf(a0, v0.w, acc.w);
        }
        __syncthreads();
    }
    float4 bb = *(const float4*)(bias + hh * CC + c4);
    acc.x += bb.x; acc.y += bb.y; acc.z += bb.z; acc.w += bb.w;
    *(float4*)(out + (size_t)dstn * HC + hh * CC + c4) = acc;
}

// ---------------- GAT aggregation, H=1 C=64, shared-alpha ----------------
__global__ void k_agg1(const float* __restrict__ h3, const float* __restrict__ ssrc,
                       const float* __restrict__ sdst, const float* __restrict__ bias,
                       float* __restrict__ out) {
    int dstn = blockIdx.x;
    int tid = threadIdx.x;
    __shared__ float sh_m, sh_sinv;
    __shared__ float sh_alpha[64];
    __shared__ int   sh_src[64];
    float sd = sdst[dstn];
    int beg = g_rowptr[dstn], end = g_rowptr[dstn + 1];
    if (tid < 32) {
        float mx = -3.4e38f;
        for (int i = beg + tid; i < end; i += 32)
            mx = fmaxf(mx, lrelu02(ssrc[g_csrc[i]] + sd));
#pragma unroll
        for (int o = 1; o < 32; o <<= 1) mx = fmaxf(mx, __shfl_xor_sync(0xffffffffu, mx, o));
        float se = 0.f;
        for (int i = beg + tid; i < end; i += 32)
            se += __expf(lrelu02(ssrc[g_csrc[i]] + sd) - mx);
#pragma unroll
        for (int o = 1; o < 32; o <<= 1) se += __shfl_xor_sync(0xffffffffu, se, o);
        if (tid == 0) { sh_m = mx; sh_sinv = 1.f / (se + 1e-16f); }
    }
    __syncthreads();
    float m = sh_m, sinv = sh_sinv;
    float acc = 0.f;
    for (int c0 = beg; c0 < end; c0 += 64) {
        int cnt = min(64, end - c0);
        if (tid < cnt) {
            int s = g_csrc[c0 + tid];
            sh_src[tid] = s;
            sh_alpha[tid] = __expf(lrelu02(ssrc[s] + sd) - m) * sinv;
        }
        __syncthreads();
        int e = 0;
        for (; e + 1 < cnt; e += 2) {
            float a0 = sh_alpha[e], a1 = sh_alpha[e + 1];
            float v0 = h3[(size_t)sh_src[e] * CC + tid];
            float v1 = h3[(size_t)sh_src[e + 1] * CC + tid];
            acc = fmaf(a0, v0, fmaf(a1, v1, acc));
        }
        if (e < cnt)
            acc = fmaf(sh_alpha[e], h3[(size_t)sh_src[e] * CC + tid], acc);
        __syncthreads();
    }
    out[(size_t)dstn * CC + tid] = acc + bias[tid];
}

// ---------------- BatchNorm stats + finalize fused (last-block pattern) ----------------
__global__ void k_bn(const float* __restrict__ x, const float* __restrict__ g,
                     const float* __restrict__ be, int Cdim, int rowsPerBlock) {
    int c = threadIdx.x;
    int b = blockIdx.x;
    int r0 = b * rowsPerBlock;
    int r1 = min(r0 + rowsPerBlock, NN);
    float s = 0.f, q = 0.f;
    for (int r = r0; r < r1; r++) {
        float v = x[(size_t)r * Cdim + c];
        s += v; q = fmaf(v, v, q);
    }
    g_bnpart[b * Cdim + c] = s;
    g_bnpart2[b * Cdim + c] = q;
    __threadfence();
    __shared__ int sh_last;
    if (c == 0) {
        int old = atomicAdd(&g_bncnt, 1);
        sh_last = (old == NBN - 1) ? 1 : 0;
    }
    __syncthreads();
    if (sh_last) {
        float ts = 0.f, tq = 0.f;
        for (int bb = 0; bb < NBN; bb++) {
            ts += g_bnpart[bb * Cdim + c];
            tq += g_bnpart2[bb * Cdim + c];
        }
        float mu = ts / (float)NN;
        float var = tq / (float)NN - mu * mu;
        var = fmaxf(var, 0.f);
        float inv = rsqrtf(var + 1e-5f);
        float sc = g[c] * inv;
        g_scale[c] = sc;
        g_shift[c] = be[c] - sc * mu;
        if (c == 0) g_bncnt = 0;
    }
}

// out = res + elu(scale*in+shift); optional bf16 split; optional score-buffer zeroing
__global__ void k_bnapply(const float* __restrict__ in, const float* __restrict__ res,
                          float* __restrict__ out,
                          __nv_bfloat16* __restrict__ outH, __nv_bfloat16* __restrict__ outL,
                          int Cdim, int doElu, int total4, int zeroScores) {
    int i0 = blockIdx.x * blockDim.x + threadIdx.x;
    int stride = gridDim.x * blockDim.x;
    if (zeroScores) {
        for (int zi = i0; zi < NN * HH; zi += stride) { g_ssrc[zi] = 0.f; g_sdst[zi] = 0.f; }
    }
    int c4cnt = Cdim >> 2;
    for (int i = i0; i < total4; i += stride) {
        int c4 = (i % c4cnt) << 2;
        float4 v = ((const float4*)in)[i];
        float4 sc = *(const float4*)&g_scale[c4];
        float4 sh = *(const float4*)&g_shift[c4];
        float o0 = fmaf(sc.x, v.x, sh.x);
        float o1 = fmaf(sc.y, v.y, sh.y);
        float o2 = fmaf(sc.z, v.z, sh.z);
        float o3 = fmaf(sc.w, v.w, sh.w);
        if (doElu) {
            o0 = o0 > 0.f ? o0 : expm1f(o0);
            o1 = o1 > 0.f ? o1 : expm1f(o1);
            o2 = o2 > 0.f ? o2 : expm1f(o2);
            o3 = o3 > 0.f ? o3 : expm1f(o3);
        }
        if (res) {
            float4 rv = ((const float4*)res)[i];
            o0 += rv.x; o1 += rv.y; o2 += rv.z; o3 += rv.w;
        }
        ((float4*)out)[i] = make_float4(o0, o1, o2, o3);
        if (outH) {
            __nv_bfloat16 h0, h1, h2, h3, l0, l1, l2, l3;
            split_bf16(o0, h0, l0); split_bf16(o1, h1, l1);
            split_bf16(o2, h2, l2); split_bf16(o3, h3, l3);
            ((__nv_bfloat162*)outH)[2 * i]     = __halves2bfloat162(h0, h1);
            ((__nv_bfloat162*)outH)[2 * i + 1] = __halves2bfloat162(h2, h3);
            ((__nv_bfloat162*)outL)[2 * i]     = __halves2bfloat162(l0, l1);
            ((__nv_bfloat162*)outL)[2 * i + 1] = __halves2bfloat162(l2, l3);
        }
    }
}

// ---------------- fused pool + classifier (batch is sorted) ----------------
__global__ void k_poolfinal(const float* __restrict__ x3, const int* __restrict__ batch,
                            const float* __restrict__ linW, const float* __restrict__ linb,
                            float* __restrict__ out) {
    int g = blockIdx.x;
    int j = threadIdx.x;
    __shared__ float xg[CC];
    int lo = 0, hi = NN;
    while (lo < hi) { int mid = (lo + hi) >> 1; if (batch[mid] < g) lo = mid + 1; else hi = mid; }
    int beg = lo;
    hi = NN;
    while (lo < hi) { int mid = (lo + hi) >> 1; if (batch[mid] <= g) lo = mid + 1; else hi = mid; }
    int end = lo;
    float s = 0.f;
    for (int n = beg; n < end; n++) s += x3[(size_t)n * CC + j];
    float cv = fmaxf((float)(end - beg), 1.0f);
    xg[j] = s / cv;
    __syncthreads();
    float acc = linb[j];
#pragma unroll
    for (int c = 0; c < CC; c++) acc = fmaf(xg[c], linW[c * NCLS + j], acc);
    out[g * NCLS + j] = acc;
}

// ---------------- host side ----------------
extern "C" void kernel_launch(void* const* d_in, const int* in_sizes, int n_in,
                              void* d_out, int out_size) {
    const float* x      = (const float*)d_in[0];
    const int*   ei     = (const int*)d_in[1];
    const int*   batch  = (const int*)d_in[2];
    const float* enc_W  = (const float*)d_in[3];
    const float* enc_b  = (const float*)d_in[4];
    const float* W1     = (const float*)d_in[5];
    const float* as1    = (const float*)d_in[6];
    const float* ad1    = (const float*)d_in[7];
    const float* b1     = (const float*)d_in[8];
    const float* g1     = (const float*)d_in[9];
    const float* be1    = (const float*)d_in[10];
    const float* W2     = (const float*)d_in[11];
    const float* as2    = (const float*)d_in[12];
    const float* ad2    = (const float*)d_in[13];
    const float* b2     = (const float*)d_in[14];
    const float* g2     = (const float*)d_in[15];
    const float* be2    = (const float*)d_in[16];
    const float* W3     = (const float*)d_in[17];
    const float* as3    = (const float*)d_in[18];
    const float* ad3    = (const float*)d_in[19];
    const float* b3     = (const float*)d_in[20];
    const float* g3     = (const float*)d_in[21];
    const float* be3    = (const float*)d_in[22];
    const float* linW   = (const float*)d_in[23];
    const float* linb   = (const float*)d_in[24];
    float* out = (float*)d_out;

    float *bufA, *bufB, *hbuf, *gat, *ssrc, *sdst, *x3, *gat3;
    __nv_bfloat16 *Ah, *Al, *Ah2, *Al2, *Wth, *Wtl;
    cudaGetSymbolAddress((void**)&bufA, g_bufA);
    cudaGetSymbolAddress((void**)&bufB, g_bufB);
    cudaGetSymbolAddress((void**)&hbuf, g_h);
    cudaGetSymbolAddress((void**)&gat,  g_gat);
    cudaGetSymbolAddress((void**)&ssrc, g_ssrc);
    cudaGetSymbolAddress((void**)&sdst, g_sdst);
    cudaGetSymbolAddress((void**)&x3,   g_x3);
    cudaGetSymbolAddress((void**)&gat3, g_gat3);
    cudaGetSymbolAddress((void**)&Ah,   g_Ah);
    cudaGetSymbolAddress((void**)&Al,   g_Al);
    cudaGetSymbolAddress((void**)&Ah2,  g_Ah2);
    cudaGetSymbolAddress((void**)&Al2,  g_Al2);
    cudaGetSymbolAddress((void**)&Wth,  g_WthA);
    cudaGetSymbolAddress((void**)&Wtl,  g_WtlA);
    __nv_bfloat16 *Wth0 = Wth,              *Wtl0 = Wtl;
    __nv_bfloat16 *Wth1 = Wth + HC * HC,    *Wtl1 = Wtl + HC * HC;
    __nv_bfloat16 *Wth2 = Wth + 2 * HC * HC,*Wtl2 = Wtl + 2 * HC * HC;
    __nv_bfloat16 *Wth3 = Wth + 3 * HC * HC,*Wtl3 = Wtl + 3 * HC * HC;

    cudaFuncSetAttribute(k_gemm_mma, cudaFuncAttributeMaxDynamicSharedMemorySize, SMEM_GEMM);

    dim3 gGrid(HC / 64, (NN + 127) / 128);    // 8 x 79
    dim3 gGrid3(1, (NN + 127) / 128);         // 1 x 79
    const int T4 = NN * HC / 4;
    const int T4c = NN * CC / 4;

    // launch 0: prep; 1: count; 2: scan+fillself; 3: encoder GEMM (ncu slot)
    k_prep<<<dim3(16, 16, 6), dim3(32, 8)>>>(x, Ah, Al, enc_W, W1, W2, W3);
    k_count<<<(EE + 255) / 256, 256>>>(ei);
    k_scanfill<<<1, 1024>>>();
    k_gemm_mma<<<gGrid, 256, SMEM_GEMM>>>(Ah, Al, Wth0, Wtl0, enc_b, bufA, Ah2, Al2,
                                          nullptr, nullptr, HH, NN, HC);
    k_fill<<<(EE + 255) / 256, 256>>>(ei);

    // ---- layer 1 ----
    k_gemm_mma<<<gGrid, 256, SMEM_GEMM>>>(Ah2, Al2, Wth1, Wtl1, nullptr, hbuf, nullptr, nullptr,
                                          as1, ad1, HH, NN, HC);
    k_agg8<<<NN, 128>>>(hbuf, ssrc, sdst, b1, gat);
    k_bn<<<NBN, HC>>>(gat, g1, be1, HC, NN / NBN);
    k_bnapply<<<512, 256>>>(gat, bufA, bufB, Ah, Al, HC, 1, T4, 1);

    // ---- layer 2 ----
    k_gemm_mma<<<gGrid, 256, SMEM_GEMM>>>(Ah, Al, Wth2, Wtl2, nullptr, hbuf, nullptr, nullptr,
                                          as2, ad2, HH, NN, HC);
    k_agg8<<<NN, 128>>>(hbuf, ssrc, sdst, b2, gat);
    k_bn<<<NBN, HC>>>(gat, g2, be2, HC, NN / NBN);
    k_bnapply<<<512, 256>>>(gat, bufB, bufA, Ah2, Al2, HC, 1, T4, 1);

    // ---- layer 3 (H=1) ----
    k_gemm_mma<<<gGrid3, 256, SMEM_GEMM>>>(Ah2, Al2, Wth3, Wtl3, nullptr, x3, nullptr, nullptr,
                                           as3, ad3, 1, NN, CC);
    k_agg1<<<NN, 64>>>(x3, ssrc, sdst, b3, gat3);
    k_bn<<<NBN, CC>>>(gat3, g3, be3, CC, NN / NBN);
    k_bnapply<<<256, 256>>>(gat3, nullptr, x3, nullptr, nullptr, CC, 0, T4c, 0);

    // ---- fused pool + classifier ----
    k_poolfinal<<<GG, NCLS>>>(x3, batch, linW, linb, out);
}

// round 14
// speedup vs baseline: 1.1217x; 1.1217x over previous
#include <cuda_runtime.h>
#include <cuda_bf16.h>
#include <math.h>
#include <stdint.h>

// Problem constants
#define NN    10000
#define EE    160000
#define EP    170000
#define HH    8
#define CC    64
#define HC    512
#define GG    64
#define NCLS  64
#define NBN   100            // bn partial blocks (serial finalize tail scales with this!)

// ---------------- device scratch ----------------
__device__ float g_bufA[NN * HC];
__device__ float g_bufB[NN * HC];
__device__ float g_h[NN * HC];
__device__ float g_gat[NN * HC];
__device__ float g_ssrc[NN * HH];
__device__ float g_sdst[NN * HH];
__device__ float g_x3[NN * CC];
__device__ float g_gat3[NN * CC];
__device__ int   g_rowptr[NN + 1];
__device__ int   g_cnt[NN];
__device__ int   g_csrc[EP];
__device__ float g_bnpart[NBN * HC];
__device__ float g_bnpart2[NBN * HC];
__device__ int   g_bncnt;
__device__ float g_scale[HC];
__device__ float g_shift[HC];
__device__ __nv_bfloat16 g_Ah[NN * HC];
__device__ __nv_bfloat16 g_Al[NN * HC];
__device__ __nv_bfloat16 g_Ah2[NN * HC];
__device__ __nv_bfloat16 g_Al2[NN * HC];
__device__ __nv_bfloat16 g_WthA[4][HC * HC];
__device__ __nv_bfloat16 g_WtlA[4][HC * HC];

// ======================= helpers =======================
__device__ __forceinline__ uint32_t smem_to_u32(const void* p) {
    uint32_t a;
    asm("{ .reg .u64 t; cvta.to.shared.u64 t, %1; cvt.u32.u64 %0, t; }" : "=r"(a) : "l"(p));
    return a;
}
__device__ __forceinline__ void ldm_x4(uint32_t* r, uint32_t addr) {
    asm volatile("ldmatrix.sync.aligned.m8n8.x4.shared.b16 {%0,%1,%2,%3}, [%4];"
                 : "=r"(r[0]), "=r"(r[1]), "=r"(r[2]), "=r"(r[3]) : "r"(addr));
}
__device__ __forceinline__ void mma16816(float* c, const uint32_t* a, const uint32_t* b) {
    asm volatile(
        "mma.sync.aligned.m16n8k16.row.col.f32.bf16.bf16.f32 "
        "{%0,%1,%2,%3}, {%4,%5,%6,%7}, {%8,%9}, {%0,%1,%2,%3};"
        : "+f"(c[0]), "+f"(c[1]), "+f"(c[2]), "+f"(c[3])
        : "r"(a[0]), "r"(a[1]), "r"(a[2]), "r"(a[3]), "r"(b[0]), "r"(b[1]));
}
__device__ __forceinline__ void cp16(uint32_t dst, const void* src, int sz) {
    asm volatile("cp.async.cg.shared.global [%0], [%1], 16, %2;"
                 :: "r"(dst), "l"(src), "r"(sz));
}
#define CP_COMMIT() asm volatile("cp.async.commit_group;" ::: "memory")
#define CP_WAIT(n)  asm volatile("cp.async.wait_group %0;" :: "n"(n) : "memory")

__device__ __forceinline__ void split_bf16(float v, __nv_bfloat16& h, __nv_bfloat16& l) {
    h = __float2bfloat16(v);
    l = __float2bfloat16(v - __bfloat162float(h));
}

// ======================= prep mega-kernel =======================
__global__ void k_prep(const float* __restrict__ x,
                       __nv_bfloat16* __restrict__ Ah, __nv_bfloat16* __restrict__ Al,
                       const float* __restrict__ W0, const float* __restrict__ W1,
                       const float* __restrict__ W2, const float* __restrict__ W3) {
    int z = blockIdx.z;
    int tx = threadIdx.x, ty = threadIdx.y;
    int tid = ty * 32 + tx;
    if (z < 4) {
        const float* W = (z == 0) ? W0 : (z == 1) ? W1 : (z == 2) ? W2 : W3;
        int Nn = (z == 3) ? CC : HC;
        int bx = blockIdx.x * 32;
        int by = blockIdx.y * 32;
        if (bx >= Nn) return;
        __shared__ float t[32][33];
#pragma unroll
        for (int j = 0; j < 32; j += 8)
            t[ty + j][tx] = W[(size_t)(by + ty + j) * Nn + bx + tx];
        __syncthreads();
        __nv_bfloat16* th = g_WthA[z];
        __nv_bfloat16* tl = g_WtlA[z];
#pragma unroll
        for (int j = 0; j < 32; j += 8) {
            float v = t[tx][ty + j];
            __nv_bfloat16 h, l;
            split_bf16(v, h, l);
            size_t o = (size_t)(bx + ty + j) * HC + by + tx;
            th[o] = h; tl[o] = l;
        }
    } else if (z == 4) {
        int i = (blockIdx.y * 16 + blockIdx.x) * 256 + tid;
        if (i == 0) g_bncnt = 0;
        if (i < NN) g_cnt[i] = 0;
        for (int s = i; s < NN * HH; s += 65536) { g_ssrc[s] = 0.f; g_sdst[s] = 0.f; }
    } else {
        const int n4 = NN * HC / 4;
        int i = (blockIdx.y * 16 + blockIdx.x) * 256 + tid;
        for (; i < n4; i += 65536) {
            float4 v = ((const float4*)x)[i];
            __nv_bfloat16 h0, h1, h2, h3, l0, l1, l2, l3;
            split_bf16(v.x, h0, l0); split_bf16(v.y, h1, l1);
            split_bf16(v.z, h2, l2); split_bf16(v.w, h3, l3);
            ((__nv_bfloat162*)Ah)[2 * i]     = __halves2bfloat162(h0, h1);
            ((__nv_bfloat162*)Ah)[2 * i + 1] = __halves2bfloat162(h2, h3);
            ((__nv_bfloat162*)Al)[2 * i]     = __halves2bfloat162(l0, l1);
            ((__nv_bfloat162*)Al)[2 * i + 1] = __halves2bfloat162(l2, l3);
        }
    }
}

// ======================= cp.async double-buffered warp-MMA GEMM =======================
// BN=64: BM=128, BK=64, 256 threads = 8 warps (4M x 2N), warp tile 32x32,
// 2 CTAs/SM (regs ~119). Proven best config (R11).
#define AH_OFF 0
#define AL_OFF 16384
#define BH_OFF 32768
#define BL_OFF 40960
#define STG    49152
#define SMEM_GEMM (2 * STG)

__global__ __launch_bounds__(256, 2)
void k_gemm_mma(const __nv_bfloat16* __restrict__ Ah, const __nv_bfloat16* __restrict__ Al,
                const __nv_bfloat16* __restrict__ Bh, const __nv_bfloat16* __restrict__ Bl,
                const float* __restrict__ bias, float* __restrict__ Cm,
                __nv_bfloat16* __restrict__ outH, __nv_bfloat16* __restrict__ outL,
                const float* __restrict__ aS, const float* __restrict__ aD, int Hh,
                int M, int Nn) {
    extern __shared__ char smem[];
    const uint32_t sb = smem_to_u32(smem);
    const int tid = threadIdx.x;
    const int lane = tid & 31;
    const int wid = tid >> 5;
    const int warpM = wid & 3;
    const int warpN = wid >> 2;
    const int bm = blockIdx.y * 128;
    const int bn = blockIdx.x * 64;

    float acc[2][4][4];
#pragma unroll
    for (int mt = 0; mt < 2; mt++)
#pragma unroll
        for (int nt = 0; nt < 4; nt++)
#pragma unroll
            for (int r = 0; r < 4; r++) acc[mt][nt][r] = 0.f;

    auto issue = [&](int kb, int buf) {
        const uint32_t sbase = sb + buf * STG;
#pragma unroll
        for (int it = 0; it < 4; it++) {
            int idx = tid + it * 256;
            int r = idx >> 3, c16 = idx & 7;
            uint32_t so = (uint32_t)(r * 128 + c16 * 16);
            so ^= (so >> 3) & 0x70;
            int gr = bm + r;
            int grc = gr < M ? gr : 0;
            int sz = gr < M ? 16 : 0;
            size_t goff = (size_t)grc * 512 + kb * 64 + c16 * 8;
            cp16(sbase + AH_OFF + so, Ah + goff, sz);
            cp16(sbase + AL_OFF + so, Al + goff, sz);
        }
#pragma unroll
        for (int it = 0; it < 2; it++) {
            int idx = tid + it * 256;
            int r = idx >> 3, c16 = idx & 7;
            uint32_t so = (uint32_t)(r * 128 + c16 * 16);
            so ^= (so >> 3) & 0x70;
            size_t goff = (size_t)(bn + r) * 512 + kb * 64 + c16 * 8;
            cp16(sbase + BH_OFF + so, Bh + goff, 16);
            cp16(sbase + BL_OFF + so, Bl + goff, 16);
        }
    };

    const uint32_t aRow = (uint32_t)(warpM * 32 + (lane & 15));
    const uint32_t aC16b = (uint32_t)(lane >> 4);
    const uint32_t bRow = (uint32_t)(warpN * 32 + ((lane >> 4) << 3) + (lane & 7));
    const uint32_t bC16b = (uint32_t)((lane >> 3) & 1);

    issue(0, 0);
    CP_COMMIT();

    for (int kb = 0; kb < 8; kb++) {
        if (kb + 1 < 8) { issue(kb + 1, (kb + 1) & 1); CP_COMMIT(); }
        if (kb + 1 < 8) { CP_WAIT(1); } else { CP_WAIT(0); }
        __syncthreads();
        const uint32_t sbase = sb + (kb & 1) * STG;
#pragma unroll
        for (int ks = 0; ks < 4; ks++) {
            uint32_t ah[2][4], al[2][4], bh[2][4], bl[2][4];
            uint32_t ac16 = (uint32_t)(ks * 2) + aC16b;
            uint32_t bc16 = (uint32_t)(ks * 2) + bC16b;
#pragma unroll
            for (int mt = 0; mt < 2; mt++) {
                uint32_t off = (aRow + mt * 16) * 128 + ac16 * 16;
                off ^= (off >> 3) & 0x70;
                ldm_x4(ah[mt], sbase + AH_OFF + off);
            }
#pragma unroll
            for (int half = 0; half < 2; half++) {
                uint32_t off = (bRow + half * 16) * 128 + bc16 * 16;
                off ^= (off >> 3) & 0x70;
                ldm_x4(bh[half], sbase + BH_OFF + off);
            }
#pragma unroll
            for (int mt = 0; mt < 2; mt++) {
                uint32_t off = (aRow + mt * 16) * 128 + ac16 * 16;
                off ^= (off >> 3) & 0x70;
                ldm_x4(al[mt], sbase + AL_OFF + off);
            }
#pragma unroll
            for (int half = 0; half < 2; half++) {
                uint32_t off = (bRow + half * 16) * 128 + bc16 * 16;
                off ^= (off >> 3) & 0x70;
                ldm_x4(bl[half], sbase + BL_OFF + off);
            }
#pragma unroll
            for (int mt = 0; mt < 2; mt++)
#pragma unroll
                for (int nt = 0; nt < 4; nt++)
                    mma16816(acc[mt][nt], ah[mt], &bh[nt >> 1][(nt & 1) * 2]);
#pragma unroll
            for (int mt = 0; mt < 2; mt++)
#pragma unroll
                for (int nt = 0; nt < 4; nt++)
                    mma16816(acc[mt][nt], al[mt], &bh[nt >> 1][(nt & 1) * 2]);
#pragma unroll
            for (int mt = 0; mt < 2; mt++)
#pragma unroll
                for (int nt = 0; nt < 4; nt++)
                    mma16816(acc[mt][nt], ah[mt], &bl[nt >> 1][(nt & 1) * 2]);
        }
        __syncthreads();
    }

    const int rowBase = bm + warpM * 32 + (lane >> 2);
    const int colBase = bn + warpN * 32 + (lane & 3) * 2;
#pragma unroll
    for (int mt = 0; mt < 2; mt++) {
#pragma unroll
        for (int nt = 0; nt < 4; nt++) {
            int gc = colBase + nt * 8;
            float b0 = 0.f, b1 = 0.f;
            if (bias) { b0 = bias[gc]; b1 = bias[gc + 1]; }
#pragma unroll
            for (int half = 0; half < 2; half++) {
                int r = rowBase + mt * 16 + half * 8;
                if (r < M) {
                    float v0 = acc[mt][nt][half * 2] + b0;
                    float v1 = acc[mt][nt][half * 2 + 1] + b1;
                    *(float2*)(Cm + (size_t)r * Nn + gc) = make_float2(v0, v1);
                    if (outH) {
                        __nv_bfloat16 h0, h1, l0, l1;
                        split_bf16(v0, h0, l0);
                        split_bf16(v1, h1, l1);
                        *(__nv_bfloat162*)(outH + (size_t)r * Nn + gc) = __halves2bfloat162(h0, h1);
                        *(__nv_bfloat162*)(outL + (size_t)r * Nn + gc) = __halves2bfloat162(l0, l1);
                    }
                }
            }
        }
    }

    // ---- fused attention score partials (head == blockIdx.x since BN == CC == 64) ----
    if (aS) {
        const int head = blockIdx.x;
        const float* aSh = aS + head * CC;
        const float* aDh = aD + head * CC;
        const int colh0 = warpN * 32 + (lane & 3) * 2;
#pragma unroll
        for (int mt = 0; mt < 2; mt++) {
#pragma unroll
            for (int half = 0; half < 2; half++) {
                float s1 = 0.f, s2 = 0.f;
#pragma unroll
                for (int nt = 0; nt < 4; nt++) {
                    int colh = colh0 + nt * 8;
                    float v0 = acc[mt][nt][half * 2];
                    float v1 = acc[mt][nt][half * 2 + 1];
                    s1 += v0 * aSh[colh] + v1 * aSh[colh + 1];
                    s2 += v0 * aDh[colh] + v1 * aDh[colh + 1];
                }
                s1 += __shfl_xor_sync(0xffffffffu, s1, 1);
                s1 += __shfl_xor_sync(0xffffffffu, s1, 2);
                s2 += __shfl_xor_sync(0xffffffffu, s2, 1);
                s2 += __shfl_xor_sync(0xffffffffu, s2, 2);
                int r = rowBase + mt * 16 + half * 8;
                if ((lane & 3) == 0 && r < M) {
                    atomicAdd(&g_ssrc[r * Hh + head], s1);
                    atomicAdd(&g_sdst[r * Hh + head], s2);
                }
            }
        }
    }
}

// ---------------- CSR build ----------------
__global__ void k_count(const int* __restrict__ ei) {
    int e = blockIdx.x * blockDim.x + threadIdx.x;
    if (e < EE) atomicAdd(&g_cnt[ei[EE + e]], 1);
}
__global__ void k_scanfill() {
    __shared__ int sh[1024];
    __shared__ int carry;
    int tid = threadIdx.x;
    if (tid == 0) carry = 0;
    __syncthreads();
    for (int base = 0; base < NN; base += 1024) {
        int i = base + tid;
        int v = (i < NN) ? (g_cnt[i] + 1) : 0;
        sh[tid] = v;
        __syncthreads();
        for (int off = 1; off < 1024; off <<= 1) {
            int t = (tid >= off) ? sh[tid - off] : 0;
            __syncthreads();
            sh[tid] += t;
            __syncthreads();
        }
        if (i < NN) g_rowptr[i + 1] = carry + sh[tid];
        __syncthreads();
        if (tid == 1023) carry += sh[1023];
        __syncthreads();
    }
    if (tid == 0) g_rowptr[0] = 0;
    __syncthreads();
    for (int i = tid; i < NN; i += 1024) {
        int rp = (i == 0) ? 0 : g_rowptr[i];
        g_csrc[rp] = i;
        g_cnt[i] = rp + 1;
    }
}
__global__ void k_fill(const int* __restrict__ ei) {
    int e = blockIdx.x * blockDim.x + threadIdx.x;
    if (e < EE) {
        int dst = ei[EE + e];
        int slot = atomicAdd(&g_cnt[dst], 1);
        g_csrc[slot] = ei[e];
    }
}

__device__ __forceinline__ float lrelu02(float x) { return x > 0.f ? x : 0.2f * x; }

// ---------------- GAT aggregation, H=8, shared-alpha ----------------
__global__ void k_agg8(const float* __restrict__ hbuf, const float* __restrict__ ssrc,
                       const float* __restrict__ sdst, const float* __restrict__ bias,
                       float* __restrict__ out) {
    int dstn = blockIdx.x;
    int tid = threadIdx.x;
    __shared__ float sh_sdst[HH], sh_m[HH], sh_sinv[HH];
    __shared__ float sh_alpha[32 * HH];
    __shared__ int   sh_src[32];
    if (tid < HH) sh_sdst[tid] = sdst[dstn * HH + tid];
    __syncthreads();
    int beg = g_rowptr[dstn], end = g_rowptr[dstn + 1];
    int warp = tid >> 5, lane = tid & 31;
    {
        int hh = warp * 2 + (lane >> 4);
        int sub = lane & 15;
        float sd = sh_sdst[hh];
        float mx = -3.4e38f;
        for (int i = beg + sub; i < end; i += 16)
            mx = fmaxf(mx, lrelu02(ssrc[g_csrc[i] * HH + hh] + sd));
#pragma unroll
        for (int o = 1; o < 16; o <<= 1) mx = fmaxf(mx, __shfl_xor_sync(0xffffffffu, mx, o));
        float se = 0.f;
        for (int i = beg + sub; i < end; i += 16)
            se += __expf(lrelu02(ssrc[g_csrc[i] * HH + hh] + sd) - mx);
#pragma unroll
        for (int o = 1; o < 16; o <<= 1) se += __shfl_xor_sync(0xffffffffu, se, o);
        if (sub == 0) { sh_m[hh] = mx; sh_sinv[hh] = 1.f / (se + 1e-16f); }
    }
    __syncthreads();
    int hh = tid >> 4;
    int c4 = (tid & 15) << 2;
    float4 acc = make_float4(0.f, 0.f, 0.f, 0.f);
    for (int c0 = beg; c0 < end; c0 += 32) {
        int cnt = min(32, end - c0);
        for (int t = tid; t < cnt * HH; t += 128) {
            int e = t >> 3, h2 = t & 7;
            int s = g_csrc[c0 + e];
            if (h2 == 0) sh_src[e] = s;
            sh_alpha[e * HH + h2] =
                __expf(lrelu02(ssrc[s * HH + h2] + sh_sdst[h2]) - sh_m[h2]) * sh_sinv[h2];
        }
        __syncthreads();
        int e = 0;
        for (; e + 1 < cnt; e += 2) {
            float a0 = sh_alpha[e * HH + hh];
            float a1 = sh_alpha[(e + 1) * HH + hh];
            float4 v0 = *(const float4*)(hbuf + (size_t)sh_src[e] * HC + hh * CC + c4);
            float4 v1 = *(const float4*)(hbuf + (size_t)sh_src[e + 1] * HC + hh * CC + c4);
            acc.x = fmaf(a0, v0.x, fmaf(a1, v1.x, acc.x));
            acc.y = fmaf(a0, v0.y, fmaf(a1, v1.y, acc.y));
            acc.z = fmaf(a0, v0.z, fmaf(a1, v1.z, acc.z));
            acc.w = fmaf(a0, v0.w, fmaf(a1, v1.w, acc.w));
        }
        if (e < cnt) {
            float a0 = sh_alpha[e * HH + hh];
            float4 v0 = *(const float4*)(hbuf + (size_t)sh_src[e] * HC + hh * CC + c4);
            acc.x = fmaf(a0, v0.x, acc.x);
            acc.y = fmaf(a0, v0.y, acc.y);
            acc.z = fmaf(a0, v0.z, acc.z);
            acc.w = fmaf(a0, v0.w, acc.w);
        }
        __syncthreads();
    }
    float4 bb = *(const float4*)(bias + hh * CC + c4);
    acc.x += bb.x; acc.y += bb.y; acc.z += bb.z; acc.w += bb.w;
    *(float4*)(out + (size_t)dstn * HC + hh * CC + c4) = acc;
}

// ---------------- GAT aggregation, H=1 C=64, shared-alpha ----------------
__global__ void k_agg1(const float* __restrict__ h3, const float* __restrict__ ssrc,
                       const float* __restrict__ sdst, const float* __restrict__ bias,
                       float* __restrict__ out) {
    int dstn = blockIdx.x;
    int tid = threadIdx.x;
    __shared__ float sh_m, sh_sinv;
    __shared__ float sh_alpha[64];
    __shared__ int   sh_src[64];
    float sd = sdst[dstn];
    int beg = g_rowptr[dstn], end = g_rowptr[dstn + 1];
    if (tid < 32) {
        float mx = -3.4e38f;
        for (int i = beg + tid; i < end; i += 32)
            mx = fmaxf(mx, lrelu02(ssrc[g_csrc[i]] + sd));
#pragma unroll
        for (int o = 1; o < 32; o <<= 1) mx = fmaxf(mx, __shfl_xor_sync(0xffffffffu, mx, o));
        float se = 0.f;
        for (int i = beg + tid; i < end; i += 32)
            se += __expf(lrelu02(ssrc[g_csrc[i]] + sd) - mx);
#pragma unroll
        for (int o = 1; o < 32; o <<= 1) se += __shfl_xor_sync(0xffffffffu, se, o);
        if (tid == 0) { sh_m = mx; sh_sinv = 1.f / (se + 1e-16f); }
    }
    __syncthreads();
    float m = sh_m, sinv = sh_sinv;
    float acc = 0.f;
    for (int c0 = beg; c0 < end; c0 += 64) {
        int cnt = min(64, end - c0);
        if (tid < cnt) {
            int s = g_csrc[c0 + tid];
            sh_src[tid] = s;
            sh_alpha[tid] = __expf(lrelu02(ssrc[s] + sd) - m) * sinv;
        }
        __syncthreads();
        int e = 0;
        for (; e + 1 < cnt; e += 2) {
            float a0 = sh_alpha[e], a1 = sh_alpha[e + 1];
            float v0 = h3[(size_t)sh_src[e] * CC + tid];
            float v1 = h3[(size_t)sh_src[e + 1] * CC + tid];
            acc = fmaf(a0, v0, fmaf(a1, v1, acc));
        }
        if (e < cnt)
            acc = fmaf(sh_alpha[e], h3[(size_t)sh_src[e] * CC + tid], acc);
        __syncthreads();
    }
    out[(size_t)dstn * CC + tid] = acc + bias[tid];
}

// ---------------- BatchNorm stats + finalize fused (last-block pattern) ----------------
__global__ void k_bn(const float* __restrict__ x, const float* __restrict__ g,
                     const float* __restrict__ be, int Cdim, int rowsPerBlock) {
    int c = threadIdx.x;
    int b = blockIdx.x;
    int r0 = b * rowsPerBlock;
    int r1 = min(r0 + rowsPerBlock, NN);
    float s = 0.f, q = 0.f;
    for (int r = r0; r < r1; r++) {
        float v = x[(size_t)r * Cdim + c];
        s += v; q = fmaf(v, v, q);
    }
    g_bnpart[b * Cdim + c] = s;
    g_bnpart2[b * Cdim + c] = q;
    __threadfence();
    __shared__ int sh_last;
    if (c == 0) {
        int old = atomicAdd(&g_bncnt, 1);
        sh_last = (old == NBN - 1) ? 1 : 0;
    }
    __syncthreads();
    if (sh_last) {
        float ts = 0.f, tq = 0.f;
#pragma unroll 4
        for (int bb = 0; bb < NBN; bb++) {
            ts += g_bnpart[bb * Cdim + c];
            tq += g_bnpart2[bb * Cdim + c];
        }
        float mu = ts / (float)NN;
        float var = tq / (float)NN - mu * mu;
        var = fmaxf(var, 0.f);
        float inv = rsqrtf(var + 1e-5f);
        float sc = g[c] * inv;
        g_scale[c] = sc;
        g_shift[c] = be[c] - sc * mu;
        if (c == 0) g_bncnt = 0;
    }
}

// out = res + elu(scale*in+shift); optional bf16 split; optional score-buffer zeroing
__global__ void k_bnapply(const float* __restrict__ in, const float* __restrict__ res,
                          float* __restrict__ out,
                          __nv_bfloat16* __restrict__ outH, __nv_bfloat16* __restrict__ outL,
                          int Cdim, int doElu, int total4, int zeroScores) {
    int i0 = blockIdx.x * blockDim.x + threadIdx.x;
    int stride = gridDim.x * blockDim.x;
    if (zeroScores) {
        for (int zi = i0; zi < NN * HH; zi += stride) { g_ssrc[zi] = 0.f; g_sdst[zi] = 0.f; }
    }
    int c4cnt = Cdim >> 2;
    for (int i = i0; i < total4; i += stride) {
        int c4 = (i % c4cnt) << 2;
        float4 v = ((const float4*)in)[i];
        float4 sc = *(const float4*)&g_scale[c4];
        float4 sh = *(const float4*)&g_shift[c4];
        float o0 = fmaf(sc.x, v.x, sh.x);
        float o1 = fmaf(sc.y, v.y, sh.y);
        float o2 = fmaf(sc.z, v.z, sh.z);
        float o3 = fmaf(sc.w, v.w, sh.w);
        if (doElu) {
            o0 = o0 > 0.f ? o0 : expm1f(o0);
            o1 = o1 > 0.f ? o1 : expm1f(o1);
            o2 = o2 > 0.f ? o2 : expm1f(o2);
            o3 = o3 > 0.f ? o3 : expm1f(o3);
        }
        if (res) {
            float4 rv = ((const float4*)res)[i];
            o0 += rv.x; o1 += rv.y; o2 += rv.z; o3 += rv.w;
        }
        ((float4*)out)[i] = make_float4(o0, o1, o2, o3);
        if (outH) {
            __nv_bfloat16 h0, h1, h2, h3, l0, l1, l2, l3;
            split_bf16(o0, h0, l0); split_bf16(o1, h1, l1);
            split_bf16(o2, h2, l2); split_bf16(o3, h3, l3);
            ((__nv_bfloat162*)outH)[2 * i]     = __halves2bfloat162(h0, h1);
            ((__nv_bfloat162*)outH)[2 * i + 1] = __halves2bfloat162(h2, h3);
            ((__nv_bfloat162*)outL)[2 * i]     = __halves2bfloat162(l0, l1);
            ((__nv_bfloat162*)outL)[2 * i + 1] = __halves2bfloat162(l2, l3);
        }
    }
}

// ---------------- fused pool + classifier (batch is sorted) ----------------
__global__ void k_poolfinal(const float* __restrict__ x3, const int* __restrict__ batch,
                            const float* __restrict__ linW, const float* __restrict__ linb,
                            float* __restrict__ out) {
    int g = blockIdx.x;
    int j = threadIdx.x;
    __shared__ float xg[CC];
    int lo = 0, hi = NN;
    while (lo < hi) { int mid = (lo + hi) >> 1; if (batch[mid] < g) lo = mid + 1; else hi = mid; }
    int beg = lo;
    hi = NN;
    while (lo < hi) { int mid = (lo + hi) >> 1; if (batch[mid] <= g) lo = mid + 1; else hi = mid; }
    int end = lo;
    float s = 0.f;
    for (int n = beg; n < end; n++) s += x3[(size_t)n * CC + j];
    float cv = fmaxf((float)(end - beg), 1.0f);
    xg[j] = s / cv;
    __syncthreads();
    float acc = linb[j];
#pragma unroll
    for (int c = 0; c < CC; c++) acc = fmaf(xg[c], linW[c * NCLS + j], acc);
    out[g * NCLS + j] = acc;
}

// ---------------- host side ----------------
extern "C" void kernel_launch(void* const* d_in, const int* in_sizes, int n_in,
                              void* d_out, int out_size) {
    const float* x      = (const float*)d_in[0];
    const int*   ei     = (const int*)d_in[1];
    const int*   batch  = (const int*)d_in[2];
    const float* enc_W  = (const float*)d_in[3];
    const float* enc_b  = (const float*)d_in[4];
    const float* W1     = (const float*)d_in[5];
    const float* as1    = (const float*)d_in[6];
    const float* ad1    = (const float*)d_in[7];
    const float* b1     = (const float*)d_in[8];
    const float* g1     = (const float*)d_in[9];
    const float* be1    = (const float*)d_in[10];
    const float* W2     = (const float*)d_in[11];
    const float* as2    = (const float*)d_in[12];
    const float* ad2    = (const float*)d_in[13];
    const float* b2     = (const float*)d_in[14];
    const float* g2     = (const float*)d_in[15];
    const float* be2    = (const float*)d_in[16];
    const float* W3     = (const float*)d_in[17];
    const float* as3    = (const float*)d_in[18];
    const float* ad3    = (const float*)d_in[19];
    const float* b3     = (const float*)d_in[20];
    const float* g3     = (const float*)d_in[21];
    const float* be3    = (const float*)d_in[22];
    const float* linW   = (const float*)d_in[23];
    const float* linb   = (const float*)d_in[24];
    float* out = (float*)d_out;

    float *bufA, *bufB, *hbuf, *gat, *ssrc, *sdst, *x3, *gat3;
    __nv_bfloat16 *Ah, *Al, *Ah2, *Al2, *Wth, *Wtl;
    cudaGetSymbolAddress((void**)&bufA, g_bufA);
    cudaGetSymbolAddress((void**)&bufB, g_bufB);
    cudaGetSymbolAddress((void**)&hbuf, g_h);
    cudaGetSymbolAddress((void**)&gat,  g_gat);
    cudaGetSymbolAddress((void**)&ssrc, g_ssrc);
    cudaGetSymbolAddress((void**)&sdst, g_sdst);
    cudaGetSymbolAddress((void**)&x3,   g_x3);
    cudaGetSymbolAddress((void**)&gat3, g_gat3);
    cudaGetSymbolAddress((void**)&Ah,   g_Ah);
    cudaGetSymbolAddress((void**)&Al,   g_Al);
    cudaGetSymbolAddress((void**)&Ah2,  g_Ah2);
    cudaGetSymbolAddress((void**)&Al2,  g_Al2);
    cudaGetSymbolAddress((void**)&Wth,  g_WthA);
    cudaGetSymbolAddress((void**)&Wtl,  g_WtlA);
    __nv_bfloat16 *Wth0 = Wth,              *Wtl0 = Wtl;
    __nv_bfloat16 *Wth1 = Wth + HC * HC,    *Wtl1 = Wtl + HC * HC;
    __nv_bfloat16 *Wth2 = Wth + 2 * HC * HC,*Wtl2 = Wtl + 2 * HC * HC;
    __nv_bfloat16 *Wth3 = Wth + 3 * HC * HC,*Wtl3 = Wtl + 3 * HC * HC;

    cudaFuncSetAttribute(k_gemm_mma, cudaFuncAttributeMaxDynamicSharedMemorySize, SMEM_GEMM);

    dim3 gGrid(HC / 64, (NN + 127) / 128);    // 8 x 79
    dim3 gGrid3(1, (NN + 127) / 128);         // 1 x 79
    const int T4 = NN * HC / 4;
    const int T4c = NN * CC / 4;

    // launch 0: prep; 1: count; 2: scan+fillself; 3: encoder GEMM (ncu slot)
    k_prep<<<dim3(16, 16, 6), dim3(32, 8)>>>(x, Ah, Al, enc_W, W1, W2, W3);
    k_count<<<(EE + 255) / 256, 256>>>(ei);
    k_scanfill<<<1, 1024>>>();
    k_gemm_mma<<<gGrid, 256, SMEM_GEMM>>>(Ah, Al, Wth0, Wtl0, enc_b, bufA, Ah2, Al2,
                                          nullptr, nullptr, HH, NN, HC);
    k_fill<<<(EE + 255) / 256, 256>>>(ei);

    // ---- layer 1 ----
    k_gemm_mma<<<gGrid, 256, SMEM_GEMM>>>(Ah2, Al2, Wth1, Wtl1, nullptr, hbuf, nullptr, nullptr,
                                          as1, ad1, HH, NN, HC);
    k_agg8<<<NN, 128>>>(hbuf, ssrc, sdst, b1, gat);
    k_bn<<<NBN, HC>>>(gat, g1, be1, HC, NN / NBN);
    k_bnapply<<<512, 256>>>(gat, bufA, bufB, Ah, Al, HC, 1, T4, 1);

    // ---- layer 2 ----
    k_gemm_mma<<<gGrid, 256, SMEM_GEMM>>>(Ah, Al, Wth2, Wtl2, nullptr, hbuf, nullptr, nullptr,
                                          as2, ad2, HH, NN, HC);
    k_agg8<<<NN, 128>>>(hbuf, ssrc, sdst, b2, gat);
    k_bn<<<NBN, HC>>>(gat, g2, be2, HC, NN / NBN);
    k_bnapply<<<512, 256>>>(gat, bufB, bufA, Ah2, Al2, HC, 1, T4, 1);

    // ---- layer 3 (H=1) ----
    k_gemm_mma<<<gGrid3, 256, SMEM_GEMM>>>(Ah2, Al2, Wth3, Wtl3, nullptr, x3, nullptr, nullptr,
                                           as3, ad3, 1, NN, CC);
    k_agg1<<<NN, 64>>>(x3, ssrc, sdst, b3, gat3);
    k_bn<<<NBN, CC>>>(gat3, g3, be3, CC, NN / NBN);
    k_bnapply<<<256, 256>>>(gat3, nullptr, x3, nullptr, nullptr, CC, 0, T4c, 0);

    // ---- fused pool + classifier ----
    k_poolfinal<<<GG, NCLS>>>(x3, batch, linW, linb, out);
}

// round 15
// speedup vs baseline: 1.1342x; 1.0112x over previous
#include <cuda_runtime.h>
#include <cuda_bf16.h>
#include <math.h>
#include <stdint.h>

// Problem constants
#define NN    10000
#define EE    160000
#define EP    170000
#define HH    8
#define CC    64
#define HC    512
#define GG    64
#define NCLS  64
#define NBK   16             // bn atomic buckets
#define ANB   8              // nodes per aggregation block

// ---------------- device scratch ----------------
__device__ float g_bufA[NN * HC];
__device__ float g_bufB[NN * HC];
__device__ float g_h[NN * HC];
__device__ float g_gat[NN * HC];
__device__ float g_ssrc[NN * HH];
__device__ float g_sdst[NN * HH];
__device__ float g_x3[NN * CC];
__device__ float g_gat3[NN * CC];
__device__ int   g_rowptr[NN + 1];
__device__ int   g_cnt[NN];
__device__ int   g_csrc[EP];
__device__ float g_bnpart[NBK * HC];
__device__ float g_bnpart2[NBK * HC];
__device__ __nv_bfloat16 g_Ah[NN * HC];
__device__ __nv_bfloat16 g_Al[NN * HC];
__device__ __nv_bfloat16 g_Ah2[NN * HC];
__device__ __nv_bfloat16 g_Al2[NN * HC];
__device__ __nv_bfloat16 g_WthA[4][HC * HC];
__device__ __nv_bfloat16 g_WtlA[4][HC * HC];

// ======================= helpers =======================
__device__ __forceinline__ uint32_t smem_to_u32(const void* p) {
    uint32_t a;
    asm("{ .reg .u64 t; cvta.to.shared.u64 t, %1; cvt.u32.u64 %0, t; }" : "=r"(a) : "l"(p));
    return a;
}
__device__ __forceinline__ void ldm_x4(uint32_t* r, uint32_t addr) {
    asm volatile("ldmatrix.sync.aligned.m8n8.x4.shared.b16 {%0,%1,%2,%3}, [%4];"
                 : "=r"(r[0]), "=r"(r[1]), "=r"(r[2]), "=r"(r[3]) : "r"(addr));
}
__device__ __forceinline__ void mma16816(float* c, const uint32_t* a, const uint32_t* b) {
    asm volatile(
        "mma.sync.aligned.m16n8k16.row.col.f32.bf16.bf16.f32 "
        "{%0,%1,%2,%3}, {%4,%5,%6,%7}, {%8,%9}, {%0,%1,%2,%3};"
        : "+f"(c[0]), "+f"(c[1]), "+f"(c[2]), "+f"(c[3])
        : "r"(a[0]), "r"(a[1]), "r"(a[2]), "r"(a[3]), "r"(b[0]), "r"(b[1]));
}
__device__ __forceinline__ void cp16(uint32_t dst, const void* src, int sz) {
    asm volatile("cp.async.cg.shared.global [%0], [%1], 16, %2;"
                 :: "r"(dst), "l"(src), "r"(sz));
}
#define CP_COMMIT() asm volatile("cp.async.commit_group;" ::: "memory")
#define CP_WAIT(n)  asm volatile("cp.async.wait_group %0;" :: "n"(n) : "memory")

__device__ __forceinline__ void split_bf16(float v, __nv_bfloat16& h, __nv_bfloat16& l) {
    h = __float2bfloat16(v);
    l = __float2bfloat16(v - __bfloat162float(h));
}

// ======================= prep mega-kernel =======================
__global__ void k_prep(const float* __restrict__ x,
                       __nv_bfloat16* __restrict__ Ah, __nv_bfloat16* __restrict__ Al,
                       const float* __restrict__ W0, const float* __restrict__ W1,
                       const float* __restrict__ W2, const float* __restrict__ W3) {
    int z = blockIdx.z;
    int tx = threadIdx.x, ty = threadIdx.y;
    int tid = ty * 32 + tx;
    if (z < 4) {
        const float* W = (z == 0) ? W0 : (z == 1) ? W1 : (z == 2) ? W2 : W3;
        int Nn = (z == 3) ? CC : HC;
        int bx = blockIdx.x * 32;
        int by = blockIdx.y * 32;
        if (bx >= Nn) return;
        __shared__ float t[32][33];
#pragma unroll
        for (int j = 0; j < 32; j += 8)
            t[ty + j][tx] = W[(size_t)(by + ty + j) * Nn + bx + tx];
        __syncthreads();
        __nv_bfloat16* th = g_WthA[z];
        __nv_bfloat16* tl = g_WtlA[z];
#pragma unroll
        for (int j = 0; j < 32; j += 8) {
            float v = t[tx][ty + j];
            __nv_bfloat16 h, l;
            split_bf16(v, h, l);
            size_t o = (size_t)(bx + ty + j) * HC + by + tx;
            th[o] = h; tl[o] = l;
        }
    } else if (z == 4) {
        int i = (blockIdx.y * 16 + blockIdx.x) * 256 + tid;
        if (i < NN) g_cnt[i] = 0;
        if (i < NBK * HC) { g_bnpart[i] = 0.f; g_bnpart2[i] = 0.f; }
        for (int s = i; s < NN * HH; s += 65536) { g_ssrc[s] = 0.f; g_sdst[s] = 0.f; }
    } else {
        const int n4 = NN * HC / 4;
        int i = (blockIdx.y * 16 + blockIdx.x) * 256 + tid;
        for (; i < n4; i += 65536) {
            float4 v = ((const float4*)x)[i];
            __nv_bfloat16 h0, h1, h2, h3, l0, l1, l2, l3;
            split_bf16(v.x, h0, l0); split_bf16(v.y, h1, l1);
            split_bf16(v.z, h2, l2); split_bf16(v.w, h3, l3);
            ((__nv_bfloat162*)Ah)[2 * i]     = __halves2bfloat162(h0, h1);
            ((__nv_bfloat162*)Ah)[2 * i + 1] = __halves2bfloat162(h2, h3);
            ((__nv_bfloat162*)Al)[2 * i]     = __halves2bfloat162(l0, l1);
            ((__nv_bfloat162*)Al)[2 * i + 1] = __halves2bfloat162(l2, l3);
        }
    }
}

// ======================= cp.async double-buffered warp-MMA GEMM =======================
// BN=64: BM=128, BK=64, 256 threads = 8 warps (4M x 2N), warp tile 32x32, 2 CTAs/SM.
// Also zeroes bn stat buckets for the NEXT aggregation (safe by stream order).
#define AH_OFF 0
#define AL_OFF 16384
#define BH_OFF 32768
#define BL_OFF 40960
#define STG    49152
#define SMEM_GEMM (2 * STG)

__global__ __launch_bounds__(256, 2)
void k_gemm_mma(const __nv_bfloat16* __restrict__ Ah, const __nv_bfloat16* __restrict__ Al,
                const __nv_bfloat16* __restrict__ Bh, const __nv_bfloat16* __restrict__ Bl,
                const float* __restrict__ bias, float* __restrict__ Cm,
                __nv_bfloat16* __restrict__ outH, __nv_bfloat16* __restrict__ outL,
                const float* __restrict__ aS, const float* __restrict__ aD, int Hh,
                int M, int Nn) {
    extern __shared__ char smem[];
    const uint32_t sb = smem_to_u32(smem);
    const int tid = threadIdx.x;
    const int lane = tid & 31;
    const int wid = tid >> 5;
    const int warpM = wid & 3;
    const int warpN = wid >> 2;
    const int bm = blockIdx.y * 128;
    const int bn = blockIdx.x * 64;

    // zero bn stat buckets for the next aggregation pass
    if (blockIdx.x == 0) {
        int z = blockIdx.y * 256 + tid;
        if (z < NBK * HC) { g_bnpart[z] = 0.f; g_bnpart2[z] = 0.f; }
    }

    float acc[2][4][4];
#pragma unroll
    for (int mt = 0; mt < 2; mt++)
#pragma unroll
        for (int nt = 0; nt < 4; nt++)
#pragma unroll
            for (int r = 0; r < 4; r++) acc[mt][nt][r] = 0.f;

    auto issue = [&](int kb, int buf) {
        const uint32_t sbase = sb + buf * STG;
#pragma unroll
        for (int it = 0; it < 4; it++) {
            int idx = tid + it * 256;
            int r = idx >> 3, c16 = idx & 7;
            uint32_t so = (uint32_t)(r * 128 + c16 * 16);
            so ^= (so >> 3) & 0x70;
            int gr = bm + r;
            int grc = gr < M ? gr : 0;
            int sz = gr < M ? 16 : 0;
            size_t goff = (size_t)grc * 512 + kb * 64 + c16 * 8;
            cp16(sbase + AH_OFF + so, Ah + goff, sz);
            cp16(sbase + AL_OFF + so, Al + goff, sz);
        }
#pragma unroll
        for (int it = 0; it < 2; it++) {
            int idx = tid + it * 256;
            int r = idx >> 3, c16 = idx & 7;
            uint32_t so = (uint32_t)(r * 128 + c16 * 16);
            so ^= (so >> 3) & 0x70;
            size_t goff = (size_t)(bn + r) * 512 + kb * 64 + c16 * 8;
            cp16(sbase + BH_OFF + so, Bh + goff, 16);
            cp16(sbase + BL_OFF + so, Bl + goff, 16);
        }
    };

    const uint32_t aRow = (uint32_t)(warpM * 32 + (lane & 15));
    const uint32_t aC16b = (uint32_t)(lane >> 4);
    const uint32_t bRow = (uint32_t)(warpN * 32 + ((lane >> 4) << 3) + (lane & 7));
    const uint32_t bC16b = (uint32_t)((lane >> 3) & 1);

    issue(0, 0);
    CP_COMMIT();

    for (int kb = 0; kb < 8; kb++) {
        if (kb + 1 < 8) { issue(kb + 1, (kb + 1) & 1); CP_COMMIT(); }
        if (kb + 1 < 8) { CP_WAIT(1); } else { CP_WAIT(0); }
        __syncthreads();
        const uint32_t sbase = sb + (kb & 1) * STG;
#pragma unroll
        for (int ks = 0; ks < 4; ks++) {
            uint32_t ah[2][4], al[2][4], bh[2][4], bl[2][4];
            uint32_t ac16 = (uint32_t)(ks * 2) + aC16b;
            uint32_t bc16 = (uint32_t)(ks * 2) + bC16b;
#pragma unroll
            for (int mt = 0; mt < 2; mt++) {
                uint32_t off = (aRow + mt * 16) * 128 + ac16 * 16;
                off ^= (off >> 3) & 0x70;
                ldm_x4(ah[mt], sbase + AH_OFF + off);
            }
#pragma unroll
            for (int half = 0; half < 2; half++) {
                uint32_t off = (bRow + half * 16) * 128 + bc16 * 16;
                off ^= (off >> 3) & 0x70;
                ldm_x4(bh[half], sbase + BH_OFF + off);
            }
#pragma unroll
            for (int mt = 0; mt < 2; mt++) {
                uint32_t off = (aRow + mt * 16) * 128 + ac16 * 16;
                off ^= (off >> 3) & 0x70;
                ldm_x4(al[mt], sbase + AL_OFF + off);
            }
#pragma unroll
            for (int half = 0; half < 2; half++) {
                uint32_t off = (bRow + half * 16) * 128 + bc16 * 16;
                off ^= (off >> 3) & 0x70;
                ldm_x4(bl[half], sbase + BL_OFF + off);
            }
#pragma unroll
            for (int mt = 0; mt < 2; mt++)
#pragma unroll
                for (int nt = 0; nt < 4; nt++)
                    mma16816(acc[mt][nt], ah[mt], &bh[nt >> 1][(nt & 1) * 2]);
#pragma unroll
            for (int mt = 0; mt < 2; mt++)
#pragma unroll
                for (int nt = 0; nt < 4; nt++)
                    mma16816(acc[mt][nt], al[mt], &bh[nt >> 1][(nt & 1) * 2]);
#pragma unroll
            for (int mt = 0; mt < 2; mt++)
#pragma unroll
                for (int nt = 0; nt < 4; nt++)
                    mma16816(acc[mt][nt], ah[mt], &bl[nt >> 1][(nt & 1) * 2]);
        }
        __syncthreads();
    }

    const int rowBase = bm + warpM * 32 + (lane >> 2);
    const int colBase = bn + warpN * 32 + (lane & 3) * 2;
#pragma unroll
    for (int mt = 0; mt < 2; mt++) {
#pragma unroll
        for (int nt = 0; nt < 4; nt++) {
            int gc = colBase + nt * 8;
            float b0 = 0.f, b1 = 0.f;
            if (bias) { b0 = bias[gc]; b1 = bias[gc + 1]; }
#pragma unroll
            for (int half = 0; half < 2; half++) {
                int r = rowBase + mt * 16 + half * 8;
                if (r < M) {
                    float v0 = acc[mt][nt][half * 2] + b0;
                    float v1 = acc[mt][nt][half * 2 + 1] + b1;
                    *(float2*)(Cm + (size_t)r * Nn + gc) = make_float2(v0, v1);
                    if (outH) {
                        __nv_bfloat16 h0, h1, l0, l1;
                        split_bf16(v0, h0, l0);
                        split_bf16(v1, h1, l1);
                        *(__nv_bfloat162*)(outH + (size_t)r * Nn + gc) = __halves2bfloat162(h0, h1);
                        *(__nv_bfloat162*)(outL + (size_t)r * Nn + gc) = __halves2bfloat162(l0, l1);
                    }
                }
            }
        }
    }

    // ---- fused attention score partials (head == blockIdx.x since BN == CC == 64) ----
    if (aS) {
        const int head = blockIdx.x;
        const float* aSh = aS + head * CC;
        const float* aDh = aD + head * CC;
        const int colh0 = warpN * 32 + (lane & 3) * 2;
#pragma unroll
        for (int mt = 0; mt < 2; mt++) {
#pragma unroll
            for (int half = 0; half < 2; half++) {
                float s1 = 0.f, s2 = 0.f;
#pragma unroll
                for (int nt = 0; nt < 4; nt++) {
                    int colh = colh0 + nt * 8;
                    float v0 = acc[mt][nt][half * 2];
                    float v1 = acc[mt][nt][half * 2 + 1];
                    s1 += v0 * aSh[colh] + v1 * aSh[colh + 1];
                    s2 += v0 * aDh[colh] + v1 * aDh[colh + 1];
                }
                s1 += __shfl_xor_sync(0xffffffffu, s1, 1);
                s1 += __shfl_xor_sync(0xffffffffu, s1, 2);
                s2 += __shfl_xor_sync(0xffffffffu, s2, 1);
                s2 += __shfl_xor_sync(0xffffffffu, s2, 2);
                int r = rowBase + mt * 16 + half * 8;
                if ((lane & 3) == 0 && r < M) {
                    atomicAdd(&g_ssrc[r * Hh + head], s1);
                    atomicAdd(&g_sdst[r * Hh + head], s2);
                }
            }
        }
    }
}

// ---------------- CSR build ----------------
__global__ void k_count(const int* __restrict__ ei) {
    int e = blockIdx.x * blockDim.x + threadIdx.x;
    if (e < EE) atomicAdd(&g_cnt[ei[EE + e]], 1);
}
__global__ void k_scanfill() {
    __shared__ int sh[1024];
    __shared__ int carry;
    int tid = threadIdx.x;
    if (tid == 0) carry = 0;
    __syncthreads();
    for (int base = 0; base < NN; base += 1024) {
        int i = base + tid;
        int v = (i < NN) ? (g_cnt[i] + 1) : 0;
        sh[tid] = v;
        __syncthreads();
        for (int off = 1; off < 1024; off <<= 1) {
            int t = (tid >= off) ? sh[tid - off] : 0;
            __syncthreads();
            sh[tid] += t;
            __syncthreads();
        }
        if (i < NN) g_rowptr[i + 1] = carry + sh[tid];
        __syncthreads();
        if (tid == 1023) carry += sh[1023];
        __syncthreads();
    }
    if (tid == 0) g_rowptr[0] = 0;
    __syncthreads();
    for (int i = tid; i < NN; i += 1024) {
        int rp = (i == 0) ? 0 : g_rowptr[i];
        g_csrc[rp] = i;
        g_cnt[i] = rp + 1;
    }
}
__global__ void k_fill(const int* __restrict__ ei) {
    int e = blockIdx.x * blockDim.x + threadIdx.x;
    if (e < EE) {
        int dst = ei[EE + e];
        int slot = atomicAdd(&g_cnt[dst], 1);
        g_csrc[slot] = ei[e];
    }
}

__device__ __forceinline__ float lrelu02(float x) { return x > 0.f ? x : 0.2f * x; }

// ---------------- GAT aggregation, H=8, 8 nodes/block + inline BN partials ----------------
__global__ void k_agg8(const float* __restrict__ hbuf, const float* __restrict__ ssrc,
                       const float* __restrict__ sdst, const float* __restrict__ bias,
                       float* __restrict__ out) {
    int tid = threadIdx.x;
    int warp = tid >> 5, lane = tid & 31;
    int hh = tid >> 4;
    int c4 = (tid & 15) << 2;
    __shared__ float sh_sdst[HH], sh_m[HH], sh_sinv[HH];
    __shared__ float sh_alpha[32 * HH];
    __shared__ int   sh_src[32];
    float4 bb = *(const float4*)(bias + hh * CC + c4);
    float4 bsum = make_float4(0.f, 0.f, 0.f, 0.f);
    float4 bsq  = make_float4(0.f, 0.f, 0.f, 0.f);
    int base = blockIdx.x * ANB;

    for (int ni = 0; ni < ANB; ni++) {
        int dstn = base + ni;
        __syncthreads();
        if (tid < HH) sh_sdst[tid] = sdst[dstn * HH + tid];
        __syncthreads();
        int beg = g_rowptr[dstn], end = g_rowptr[dstn + 1];
        {
            int hh2 = warp * 2 + (lane >> 4);
            int sub = lane & 15;
            float sd = sh_sdst[hh2];
            float mx = -3.4e38f;
            for (int i = beg + sub; i < end; i += 16)
                mx = fmaxf(mx, lrelu02(ssrc[g_csrc[i] * HH + hh2] + sd));
#pragma unroll
            for (int o = 1; o < 16; o <<= 1) mx = fmaxf(mx, __shfl_xor_sync(0xffffffffu, mx, o));
            float se = 0.f;
            for (int i = beg + sub; i < end; i += 16)
                se += __expf(lrelu02(ssrc[g_csrc[i] * HH + hh2] + sd) - mx);
#pragma unroll
            for (int o = 1; o < 16; o <<= 1) se += __shfl_xor_sync(0xffffffffu, se, o);
            if (sub == 0) { sh_m[hh2] = mx; sh_sinv[hh2] = 1.f / (se + 1e-16f); }
        }
        __syncthreads();
        float4 acc = make_float4(0.f, 0.f, 0.f, 0.f);
        for (int c0 = beg; c0 < end; c0 += 32) {
            int cnt = min(32, end - c0);
            for (int t = tid; t < cnt * HH; t += 128) {
                int e = t >> 3, h2 = t & 7;
                int s = g_csrc[c0 + e];
                if (h2 == 0) sh_src[e] = s;
                sh_alpha[e * HH + h2] =
                    __expf(lrelu02(ssrc[s * HH + h2] + sh_sdst[h2]) - sh_m[h2]) * sh_sinv[h2];
            }
            __syncthreads();
            int e = 0;
            for (; e + 1 < cnt; e += 2) {
                float a0 = sh_alpha[e * HH + hh];
                float a1 = sh_alpha[(e + 1) * HH + hh];
                float4 v0 = *(const float4*)(hbuf + (size_t)sh_src[e] * HC + hh * CC + c4);
                float4 v1 = *(const float4*)(hbuf + (size_t)sh_src[e + 1] * HC + hh * CC + c4);
                acc.x = fmaf(a0, v0.x, fmaf(a1, v1.x, acc.x));
                acc.y = fmaf(a0, v0.y, fmaf(a1, v1.y, acc.y));
                acc.z = fmaf(a0, v0.z, fmaf(a1, v1.z, acc.z));
                acc.w = fmaf(a0, v0.w, fmaf(a1, v1.w, acc.w));
            }
            if (e < cnt) {
                float a0 = sh_alpha[e * HH + hh];
                float4 v0 = *(const float4*)(hbuf + (size_t)sh_src[e] * HC + hh * CC + c4);
                acc.x = fmaf(a0, v0.x, acc.x);
                acc.y = fmaf(a0, v0.y, acc.y);
                acc.z = fmaf(a0, v0.z, acc.z);
                acc.w = fmaf(a0, v0.w, acc.w);
            }
            __syncthreads();
        }
        float o0 = acc.x + bb.x, o1 = acc.y + bb.y;
        float o2 = acc.z + bb.z, o3 = acc.w + bb.w;
        *(float4*)(out + (size_t)dstn * HC + hh * CC + c4) = make_float4(o0, o1, o2, o3);
        bsum.x += o0; bsum.y += o1; bsum.z += o2; bsum.w += o3;
        bsq.x = fmaf(o0, o0, bsq.x); bsq.y = fmaf(o1, o1, bsq.y);
        bsq.z = fmaf(o2, o2, bsq.z); bsq.w = fmaf(o3, o3, bsq.w);
    }
    int bucket = blockIdx.x & (NBK - 1);
    float* p1 = g_bnpart  + bucket * HC + hh * CC + c4;
    float* p2 = g_bnpart2 + bucket * HC + hh * CC + c4;
    atomicAdd(p1 + 0, bsum.x); atomicAdd(p1 + 1, bsum.y);
    atomicAdd(p1 + 2, bsum.z); atomicAdd(p1 + 3, bsum.w);
    atomicAdd(p2 + 0, bsq.x);  atomicAdd(p2 + 1, bsq.y);
    atomicAdd(p2 + 2, bsq.z);  atomicAdd(p2 + 3, bsq.w);
}

// ---------------- GAT aggregation, H=1 C=64, 8 nodes/block + inline BN partials ----------------
__global__ void k_agg1(const float* __restrict__ h3, const float* __restrict__ ssrc,
                       const float* __restrict__ sdst, const float* __restrict__ bias,
                       float* __restrict__ out) {
    int tid = threadIdx.x;
    __shared__ float sh_m, sh_sinv;
    __shared__ float sh_alpha[64];
    __shared__ int   sh_src[64];
    float bbias = bias[tid];
    float bsum = 0.f, bsq = 0.f;
    int base = blockIdx.x * ANB;

    for (int ni = 0; ni < ANB; ni++) {
        int dstn = base + ni;
        float sd = sdst[dstn];
        int beg = g_rowptr[dstn], end = g_rowptr[dstn + 1];
        __syncthreads();
        if (tid < 32) {
            float mx = -3.4e38f;
            for (int i = beg + tid; i < end; i += 32)
                mx = fmaxf(mx, lrelu02(ssrc[g_csrc[i]] + sd));
#pragma unroll
            for (int o = 1; o < 32; o <<= 1) mx = fmaxf(mx, __shfl_xor_sync(0xffffffffu, mx, o));
            float se = 0.f;
            for (int i = beg + tid; i < end; i += 32)
                se += __expf(lrelu02(ssrc[g_csrc[i]] + sd) - mx);
#pragma unroll
            for (int o = 1; o < 32; o <<= 1) se += __shfl_xor_sync(0xffffffffu, se, o);
            if (tid == 0) { sh_m = mx; sh_sinv = 1.f / (se + 1e-16f); }
        }
        __syncthreads();
        float m = sh_m, sinv = sh_sinv;
        float acc = 0.f;
        for (int c0 = beg; c0 < end; c0 += 64) {
            int cnt = min(64, end - c0);
            if (tid < cnt) {
                int s = g_csrc[c0 + tid];
                sh_src[tid] = s;
                sh_alpha[tid] = __expf(lrelu02(ssrc[s] + sd) - m) * sinv;
            }
            __syncthreads();
            int e = 0;
            for (; e + 1 < cnt; e += 2) {
                float a0 = sh_alpha[e], a1 = sh_alpha[e + 1];
                float v0 = h3[(size_t)sh_src[e] * CC + tid];
                float v1 = h3[(size_t)sh_src[e + 1] * CC + tid];
                acc = fmaf(a0, v0, fmaf(a1, v1, acc));
            }
            if (e < cnt)
                acc = fmaf(sh_alpha[e], h3[(size_t)sh_src[e] * CC + tid], acc);
            __syncthreads();
        }
        float o = acc + bbias;
        out[(size_t)dstn * CC + tid] = o;
        bsum += o;
        bsq = fmaf(o, o, bsq);
    }
    int bucket = blockIdx.x & (NBK - 1);
    atomicAdd(&g_bnpart[bucket * CC + tid], bsum);
    atomicAdd(&g_bnpart2[bucket * CC + tid], bsq);
}

// ---------------- BN finalize (inline) + apply; optional bf16 split + score zeroing ----------------
__global__ void k_bnapply(const float* __restrict__ in, const float* __restrict__ res,
                          float* __restrict__ out,
                          __nv_bfloat16* __restrict__ outH, __nv_bfloat16* __restrict__ outL,
                          const float* __restrict__ g, const float* __restrict__ be,
                          int Cdim, int doElu, int total4, int zeroScores) {
    __shared__ float s_scale[HC], s_shift[HC];
    for (int c = threadIdx.x; c < Cdim; c += blockDim.x) {
        float ts = 0.f, tq = 0.f;
#pragma unroll
        for (int b = 0; b < NBK; b++) {
            ts += g_bnpart[b * Cdim + c];
            tq += g_bnpart2[b * Cdim + c];
        }
        float mu = ts / (float)NN;
        float var = tq / (float)NN - mu * mu;
        var = fmaxf(var, 0.f);
        float inv = rsqrtf(var + 1e-5f);
        float sc = g[c] * inv;
        s_scale[c] = sc;
        s_shift[c] = be[c] - sc * mu;
    }
    __syncthreads();

    int i0 = blockIdx.x * blockDim.x + threadIdx.x;
    int stride = gridDim.x * blockDim.x;
    if (zeroScores) {
        for (int zi = i0; zi < NN * HH; zi += stride) { g_ssrc[zi] = 0.f; g_sdst[zi] = 0.f; }
    }
    int c4cnt = Cdim >> 2;
    for (int i = i0; i < total4; i += stride) {
        int c4 = (i % c4cnt) << 2;
        float4 v = ((const float4*)in)[i];
        float4 sc = *(const float4*)&s_scale[c4];
        float4 sh = *(const float4*)&s_shift[c4];
        float o0 = fmaf(sc.x, v.x, sh.x);
        float o1 = fmaf(sc.y, v.y, sh.y);
        float o2 = fmaf(sc.z, v.z, sh.z);
        float o3 = fmaf(sc.w, v.w, sh.w);
        if (doElu) {
            o0 = o0 > 0.f ? o0 : expm1f(o0);
            o1 = o1 > 0.f ? o1 : expm1f(o1);
            o2 = o2 > 0.f ? o2 : expm1f(o2);
            o3 = o3 > 0.f ? o3 : expm1f(o3);
        }
        if (res) {
            float4 rv = ((const float4*)res)[i];
            o0 += rv.x; o1 += rv.y; o2 += rv.z; o3 += rv.w;
        }
        ((float4*)out)[i] = make_float4(o0, o1, o2, o3);
        if (outH) {
            __nv_bfloat16 h0, h1, h2, h3, l0, l1, l2, l3;
            split_bf16(o0, h0, l0); split_bf16(o1, h1, l1);
            split_bf16(o2, h2, l2); split_bf16(o3, h3, l3);
            ((__nv_bfloat162*)outH)[2 * i]     = __halves2bfloat162(h0, h1);
            ((__nv_bfloat162*)outH)[2 * i + 1] = __halves2bfloat162(h2, h3);
            ((__nv_bfloat162*)outL)[2 * i]     = __halves2bfloat162(l0, l1);
            ((__nv_bfloat162*)outL)[2 * i + 1] = __halves2bfloat162(l2, l3);
        }
    }
}

// ---------------- fused pool + classifier (batch is sorted) ----------------
__global__ void k_poolfinal(const float* __restrict__ x3, const int* __restrict__ batch,
                            const float* __restrict__ linW, const float* __restrict__ linb,
                            float* __restrict__ out) {
    int g = blockIdx.x;
    int j = threadIdx.x;
    __shared__ float xg[CC];
    int lo = 0, hi = NN;
    while (lo < hi) { int mid = (lo + hi) >> 1; if (batch[mid] < g) lo = mid + 1; else hi = mid; }
    int beg = lo;
    hi = NN;
    while (lo < hi) { int mid = (lo + hi) >> 1; if (batch[mid] <= g) lo = mid + 1; else hi = mid; }
    int end = lo;
    float s = 0.f;
    for (int n = beg; n < end; n++) s += x3[(size_t)n * CC + j];
    float cv = fmaxf((float)(end - beg), 1.0f);
    xg[j] = s / cv;
    __syncthreads();
    float acc = linb[j];
#pragma unroll
    for (int c = 0; c < CC; c++) acc = fmaf(xg[c], linW[c * NCLS + j], acc);
    out[g * NCLS + j] = acc;
}

// ---------------- host side ----------------
extern "C" void kernel_launch(void* const* d_in, const int* in_sizes, int n_in,
                              void* d_out, int out_size) {
    const float* x      = (const float*)d_in[0];
    const int*   ei     = (const int*)d_in[1];
    const int*   batch  = (const int*)d_in[2];
    const float* enc_W  = (const float*)d_in[3];
    const float* enc_b  = (const float*)d_in[4];
    const float* W1     = (const float*)d_in[5];
    const float* as1    = (const float*)d_in[6];
    const float* ad1    = (const float*)d_in[7];
    const float* b1     = (const float*)d_in[8];
    const float* g1     = (const float*)d_in[9];
    const float* be1    = (const float*)d_in[10];
    const float* W2     = (const float*)d_in[11];
    const float* as2    = (const float*)d_in[12];
    const float* ad2    = (const float*)d_in[13];
    const float* b2     = (const float*)d_in[14];
    const float* g2     = (const float*)d_in[15];
    const float* be2    = (const float*)d_in[16];
    const float* W3     = (const float*)d_in[17];
    const float* as3    = (const float*)d_in[18];
    const float* ad3    = (const float*)d_in[19];
    const float* b3     = (const float*)d_in[20];
    const float* g3     = (const float*)d_in[21];
    const float* be3    = (const float*)d_in[22];
    const float* linW   = (const float*)d_in[23];
    const float* linb   = (const float*)d_in[24];
    float* out = (float*)d_out;

    float *bufA, *bufB, *hbuf, *gat, *ssrc, *sdst, *x3, *gat3;
    __nv_bfloat16 *Ah, *Al, *Ah2, *Al2, *Wth, *Wtl;
    cudaGetSymbolAddress((void**)&bufA, g_bufA);
    cudaGetSymbolAddress((void**)&bufB, g_bufB);
    cudaGetSymbolAddress((void**)&hbuf, g_h);
    cudaGetSymbolAddress((void**)&gat,  g_gat);
    cudaGetSymbolAddress((void**)&ssrc, g_ssrc);
    cudaGetSymbolAddress((void**)&sdst, g_sdst);
    cudaGetSymbolAddress((void**)&x3,   g_x3);
    cudaGetSymbolAddress((void**)&gat3, g_gat3);
    cudaGetSymbolAddress((void**)&Ah,   g_Ah);
    cudaGetSymbolAddress((void**)&Al,   g_Al);
    cudaGetSymbolAddress((void**)&Ah2,  g_Ah2);
    cudaGetSymbolAddress((void**)&Al2,  g_Al2);
    cudaGetSymbolAddress((void**)&Wth,  g_WthA);
    cudaGetSymbolAddress((void**)&Wtl,  g_WtlA);
    __nv_bfloat16 *Wth0 = Wth,              *Wtl0 = Wtl;
    __nv_bfloat16 *Wth1 = Wth + HC * HC,    *Wtl1 = Wtl + HC * HC;
    __nv_bfloat16 *Wth2 = Wth + 2 * HC * HC,*Wtl2 = Wtl + 2 * HC * HC;
    __nv_bfloat16 *Wth3 = Wth + 3 * HC * HC,*Wtl3 = Wtl + 3 * HC * HC;

    cudaFuncSetAttribute(k_gemm_mma, cudaFuncAttributeMaxDynamicSharedMemorySize, SMEM_GEMM);

    dim3 gGrid(HC / 64, (NN + 127) / 128);    // 8 x 79
    dim3 gGrid3(1, (NN + 127) / 128);         // 1 x 79
    const int T4 = NN * HC / 4;
    const int T4c = NN * CC / 4;
    const int AGB = NN / ANB;                 // 1250 aggregation blocks

    // launch 0: prep; 1: count; 2: scan+fillself; 3: encoder GEMM (ncu slot)
    k_prep<<<dim3(16, 16, 6), dim3(32, 8)>>>(x, Ah, Al, enc_W, W1, W2, W3);
    k_count<<<(EE + 255) / 256, 256>>>(ei);
    k_scanfill<<<1, 1024>>>();
    k_gemm_mma<<<gGrid, 256, SMEM_GEMM>>>(Ah, Al, Wth0, Wtl0, enc_b, bufA, Ah2, Al2,
                                          nullptr, nullptr, HH, NN, HC);
    k_fill<<<(EE + 255) / 256, 256>>>(ei);

    // ---- layer 1 ----
    k_gemm_mma<<<gGrid, 256, SMEM_GEMM>>>(Ah2, Al2, Wth1, Wtl1, nullptr, hbuf, nullptr, nullptr,
                                          as1, ad1, HH, NN, HC);
    k_agg8<<<AGB, 128>>>(hbuf, ssrc, sdst, b1, gat);
    k_bnapply<<<512, 256>>>(gat, bufA, bufB, Ah, Al, g1, be1, HC, 1, T4, 1);

    // ---- layer 2 ----
    k_gemm_mma<<<gGrid, 256, SMEM_GEMM>>>(Ah, Al, Wth2, Wtl2, nullptr, hbuf, nullptr, nullptr,
                                          as2, ad2, HH, NN, HC);
    k_agg8<<<AGB, 128>>>(hbuf, ssrc, sdst, b2, gat);
    k_bnapply<<<512, 256>>>(gat, bufB, bufA, Ah2, Al2, g2, be2, HC, 1, T4, 1);

    // ---- layer 3 (H=1) ----
    k_gemm_mma<<<gGrid3, 256, SMEM_GEMM>>>(Ah2, Al2, Wth3, Wtl3, nullptr, x3, nullptr, nullptr,
                                           as3, ad3, 1, NN, CC);
    k_agg1<<<AGB, 64>>>(x3, ssrc, sdst, b3, gat3);
    k_bnapply<<<256, 256>>>(gat3, nullptr, x3, nullptr, nullptr, g3, be3, CC, 0, T4c, 0);

    // ---- fused pool + classifier ----
    k_poolfinal<<<GG, NCLS>>>(x3, batch, linW, linb, out);
}

// round 16
// speedup vs baseline: 1.1470x; 1.0113x over previous
#include <cuda_runtime.h>
#include <cuda_bf16.h>
#include <math.h>
#include <stdint.h>

// Problem constants
#define NN    10000
#define EE    160000
#define EP    170000
#define HH    8
#define CC    64
#define HC    512
#define GG    64
#define NCLS  64
#define NBK   16             // bn atomic buckets
#define ANB   8              // nodes per aggregation block

// ---------------- device scratch ----------------
__device__ float g_bufA[NN * HC];
__device__ float g_bufB[NN * HC];
__device__ float g_h[NN * HC];
__device__ float g_gat[NN * HC];
__device__ float g_ssrc[NN * HH];
__device__ float g_sdst[NN * HH];
__device__ float g_x3[NN * CC];
__device__ float g_gat3[NN * CC];
__device__ int   g_rowptr[NN + 1];
__device__ int   g_cnt[NN];
__device__ int   g_csrc[EP];
__device__ float g_bnpart[NBK * HC];
__device__ float g_bnpart2[NBK * HC];
__device__ __nv_bfloat16 g_Ah[NN * HC];
__device__ __nv_bfloat16 g_Al[NN * HC];
__device__ __nv_bfloat16 g_Ah2[NN * HC];
__device__ __nv_bfloat16 g_Al2[NN * HC];
__device__ __nv_bfloat16 g_WthA[4][HC * HC];
__device__ __nv_bfloat16 g_WtlA[4][HC * HC];

// ======================= helpers =======================
__device__ __forceinline__ uint32_t smem_to_u32(const void* p) {
    uint32_t a;
    asm("{ .reg .u64 t; cvta.to.shared.u64 t, %1; cvt.u32.u64 %0, t; }" : "=r"(a) : "l"(p));
    return a;
}
__device__ __forceinline__ void ldm_x4(uint32_t* r, uint32_t addr) {
    asm volatile("ldmatrix.sync.aligned.m8n8.x4.shared.b16 {%0,%1,%2,%3}, [%4];"
                 : "=r"(r[0]), "=r"(r[1]), "=r"(r[2]), "=r"(r[3]) : "r"(addr));
}
__device__ __forceinline__ void mma16816(float* c, const uint32_t* a, const uint32_t* b) {
    asm volatile(
        "mma.sync.aligned.m16n8k16.row.col.f32.bf16.bf16.f32 "
        "{%0,%1,%2,%3}, {%4,%5,%6,%7}, {%8,%9}, {%0,%1,%2,%3};"
        : "+f"(c[0]), "+f"(c[1]), "+f"(c[2]), "+f"(c[3])
        : "r"(a[0]), "r"(a[1]), "r"(a[2]), "r"(a[3]), "r"(b[0]), "r"(b[1]));
}
__device__ __forceinline__ void cp16(uint32_t dst, const void* src, int sz) {
    asm volatile("cp.async.cg.shared.global [%0], [%1], 16, %2;"
                 :: "r"(dst), "l"(src), "r"(sz));
}
#define CP_COMMIT() asm volatile("cp.async.commit_group;" ::: "memory")
#define CP_WAIT(n)  asm volatile("cp.async.wait_group %0;" :: "n"(n) : "memory")

__device__ __forceinline__ void split_bf16(float v, __nv_bfloat16& h, __nv_bfloat16& l) {
    h = __float2bfloat16(v);
    l = __float2bfloat16(v - __bfloat162float(h));
}

// ======================= prep mega-kernel =======================
// z=0..3: weight transpose+split; z=4: zero buckets/scores; z=5: input split;
// z=6: CSR degree count (g_cnt zeroed by memset BEFORE this kernel).
__global__ void k_prep(const float* __restrict__ x,
                       __nv_bfloat16* __restrict__ Ah, __nv_bfloat16* __restrict__ Al,
                       const float* __restrict__ W0, const float* __restrict__ W1,
                       const float* __restrict__ W2, const float* __restrict__ W3,
                       const int* __restrict__ ei) {
    int z = blockIdx.z;
    int tx = threadIdx.x, ty = threadIdx.y;
    int tid = ty * 32 + tx;
    if (z < 4) {
        const float* W = (z == 0) ? W0 : (z == 1) ? W1 : (z == 2) ? W2 : W3;
        int Nn = (z == 3) ? CC : HC;
        int bx = blockIdx.x * 32;
        int by = blockIdx.y * 32;
        if (bx >= Nn) return;
        __shared__ float t[32][33];
#pragma unroll
        for (int j = 0; j < 32; j += 8)
            t[ty + j][tx] = W[(size_t)(by + ty + j) * Nn + bx + tx];
        __syncthreads();
        __nv_bfloat16* th = g_WthA[z];
        __nv_bfloat16* tl = g_WtlA[z];
#pragma unroll
        for (int j = 0; j < 32; j += 8) {
            float v = t[tx][ty + j];
            __nv_bfloat16 h, l;
            split_bf16(v, h, l);
            size_t o = (size_t)(bx + ty + j) * HC + by + tx;
            th[o] = h; tl[o] = l;
        }
    } else if (z == 4) {
        int i = (blockIdx.y * 16 + blockIdx.x) * 256 + tid;
        if (i < NBK * HC) { g_bnpart[i] = 0.f; g_bnpart2[i] = 0.f; }
        for (int s = i; s < NN * HH; s += 65536) { g_ssrc[s] = 0.f; g_sdst[s] = 0.f; }
    } else if (z == 5) {
        const int n4 = NN * HC / 4;
        int i = (blockIdx.y * 16 + blockIdx.x) * 256 + tid;
        for (; i < n4; i += 65536) {
            float4 v = ((const float4*)x)[i];
            __nv_bfloat16 h0, h1, h2, h3, l0, l1, l2, l3;
            split_bf16(v.x, h0, l0); split_bf16(v.y, h1, l1);
            split_bf16(v.z, h2, l2); split_bf16(v.w, h3, l3);
            ((__nv_bfloat162*)Ah)[2 * i]     = __halves2bfloat162(h0, h1);
            ((__nv_bfloat162*)Ah)[2 * i + 1] = __halves2bfloat162(h2, h3);
            ((__nv_bfloat162*)Al)[2 * i]     = __halves2bfloat162(l0, l1);
            ((__nv_bfloat162*)Al)[2 * i + 1] = __halves2bfloat162(l2, l3);
        }
    } else {
        // CSR degree count
        int e = (blockIdx.y * 16 + blockIdx.x) * 256 + tid;
        for (; e < EE; e += 65536)
            atomicAdd(&g_cnt[ei[EE + e]], 1);
    }
}

// ======================= cp.async double-buffered warp-MMA GEMM =======================
// BN=64: BM=128, BK=64, 256 threads = 8 warps (4M x 2N), warp tile 32x32, 2 CTAs/SM.
// Also zeroes bn stat buckets for the NEXT aggregation (safe by stream order).
#define AH_OFF 0
#define AL_OFF 16384
#define BH_OFF 32768
#define BL_OFF 40960
#define STG    49152
#define SMEM_GEMM (2 * STG)

__global__ __launch_bounds__(256, 2)
void k_gemm_mma(const __nv_bfloat16* __restrict__ Ah, const __nv_bfloat16* __restrict__ Al,
                const __nv_bfloat16* __restrict__ Bh, const __nv_bfloat16* __restrict__ Bl,
                const float* __restrict__ bias, float* __restrict__ Cm,
                __nv_bfloat16* __restrict__ outH, __nv_bfloat16* __restrict__ outL,
                const float* __restrict__ aS, const float* __restrict__ aD, int Hh,
                int M, int Nn) {
    extern __shared__ char smem[];
    const uint32_t sb = smem_to_u32(smem);
    const int tid = threadIdx.x;
    const int lane = tid & 31;
    const int wid = tid >> 5;
    const int warpM = wid & 3;
    const int warpN = wid >> 2;
    const int bm = blockIdx.y * 128;
    const int bn = blockIdx.x * 64;

    // zero bn stat buckets for the next aggregation pass
    if (blockIdx.x == 0) {
        int z = blockIdx.y * 256 + tid;
        if (z < NBK * HC) { g_bnpart[z] = 0.f; g_bnpart2[z] = 0.f; }
    }

    float acc[2][4][4];
#pragma unroll
    for (int mt = 0; mt < 2; mt++)
#pragma unroll
        for (int nt = 0; nt < 4; nt++)
#pragma unroll
            for (int r = 0; r < 4; r++) acc[mt][nt][r] = 0.f;

    auto issue = [&](int kb, int buf) {
        const uint32_t sbase = sb + buf * STG;
#pragma unroll
        for (int it = 0; it < 4; it++) {
            int idx = tid + it * 256;
            int r = idx >> 3, c16 = idx & 7;
            uint32_t so = (uint32_t)(r * 128 + c16 * 16);
            so ^= (so >> 3) & 0x70;
            int gr = bm + r;
            int grc = gr < M ? gr : 0;
            int sz = gr < M ? 16 : 0;
            size_t goff = (size_t)grc * 512 + kb * 64 + c16 * 8;
            cp16(sbase + AH_OFF + so, Ah + goff, sz);
            cp16(sbase + AL_OFF + so, Al + goff, sz);
        }
#pragma unroll
        for (int it = 0; it < 2; it++) {
            int idx = tid + it * 256;
            int r = idx >> 3, c16 = idx & 7;
            uint32_t so = (uint32_t)(r * 128 + c16 * 16);
            so ^= (so >> 3) & 0x70;
            size_t goff = (size_t)(bn + r) * 512 + kb * 64 + c16 * 8;
            cp16(sbase + BH_OFF + so, Bh + goff, 16);
            cp16(sbase + BL_OFF + so, Bl + goff, 16);
        }
    };

    const uint32_t aRow = (uint32_t)(warpM * 32 + (lane & 15));
    const uint32_t aC16b = (uint32_t)(lane >> 4);
    const uint32_t bRow = (uint32_t)(warpN * 32 + ((lane >> 4) << 3) + (lane & 7));
    const uint32_t bC16b = (uint32_t)((lane >> 3) & 1);

    issue(0, 0);
    CP_COMMIT();

    for (int kb = 0; kb < 8; kb++) {
        if (kb + 1 < 8) { issue(kb + 1, (kb + 1) & 1); CP_COMMIT(); }
        if (kb + 1 < 8) { CP_WAIT(1); } else { CP_WAIT(0); }
        __syncthreads();
        const uint32_t sbase = sb + (kb & 1) * STG;
#pragma unroll
        for (int ks = 0; ks < 4; ks++) {
            uint32_t ah[2][4], al[2][4], bh[2][4], bl[2][4];
            uint32_t ac16 = (uint32_t)(ks * 2) + aC16b;
            uint32_t bc16 = (uint32_t)(ks * 2) + bC16b;
#pragma unroll
            for (int mt = 0; mt < 2; mt++) {
                uint32_t off = (aRow + mt * 16) * 128 + ac16 * 16;
                off ^= (off >> 3) & 0x70;
                ldm_x4(ah[mt], sbase + AH_OFF + off);
            }
#pragma unroll
            for (int half = 0; half < 2; half++) {
                uint32_t off = (bRow + half * 16) * 128 + bc16 * 16;
                off ^= (off >> 3) & 0x70;
                ldm_x4(bh[half], sbase + BH_OFF + off);
            }
#pragma unroll
            for (int mt = 0; mt < 2; mt++) {
                uint32_t off = (aRow + mt * 16) * 128 + ac16 * 16;
                off ^= (off >> 3) & 0x70;
                ldm_x4(al[mt], sbase + AL_OFF + off);
            }
#pragma unroll
            for (int half = 0; half < 2; half++) {
                uint32_t off = (bRow + half * 16) * 128 + bc16 * 16;
                off ^= (off >> 3) & 0x70;
                ldm_x4(bl[half], sbase + BL_OFF + off);
            }
#pragma unroll
            for (int mt = 0; mt < 2; mt++)
#pragma unroll
                for (int nt = 0; nt < 4; nt++)
                    mma16816(acc[mt][nt], ah[mt], &bh[nt >> 1][(nt & 1) * 2]);
#pragma unroll
            for (int mt = 0; mt < 2; mt++)
#pragma unroll
                for (int nt = 0; nt < 4; nt++)
                    mma16816(acc[mt][nt], al[mt], &bh[nt >> 1][(nt & 1) * 2]);
#pragma unroll
            for (int mt = 0; mt < 2; mt++)
#pragma unroll
                for (int nt = 0; nt < 4; nt++)
                    mma16816(acc[mt][nt], ah[mt], &bl[nt >> 1][(nt & 1) * 2]);
        }
        __syncthreads();
    }

    const int rowBase = bm + warpM * 32 + (lane >> 2);
    const int colBase = bn + warpN * 32 + (lane & 3) * 2;
#pragma unroll
    for (int mt = 0; mt < 2; mt++) {
#pragma unroll
        for (int nt = 0; nt < 4; nt++) {
            int gc = colBase + nt * 8;
            float b0 = 0.f, b1 = 0.f;
            if (bias) { b0 = bias[gc]; b1 = bias[gc + 1]; }
#pragma unroll
            for (int half = 0; half < 2; half++) {
                int r = rowBase + mt * 16 + half * 8;
                if (r < M) {
                    float v0 = acc[mt][nt][half * 2] + b0;
                    float v1 = acc[mt][nt][half * 2 + 1] + b1;
                    *(float2*)(Cm + (size_t)r * Nn + gc) = make_float2(v0, v1);
                    if (outH) {
                        __nv_bfloat16 h0, h1, l0, l1;
                        split_bf16(v0, h0, l0);
                        split_bf16(v1, h1, l1);
                        *(__nv_bfloat162*)(outH + (size_t)r * Nn + gc) = __halves2bfloat162(h0, h1);
                        *(__nv_bfloat162*)(outL + (size_t)r * Nn + gc) = __halves2bfloat162(l0, l1);
                    }
                }
            }
        }
    }

    // ---- fused attention score partials (head == blockIdx.x since BN == CC == 64) ----
    if (aS) {
        const int head = blockIdx.x;
        const float* aSh = aS + head * CC;
        const float* aDh = aD + head * CC;
        const int colh0 = warpN * 32 + (lane & 3) * 2;
#pragma unroll
        for (int mt = 0; mt < 2; mt++) {
#pragma unroll
            for (int half = 0; half < 2; half++) {
                float s1 = 0.f, s2 = 0.f;
#pragma unroll
                for (int nt = 0; nt < 4; nt++) {
                    int colh = colh0 + nt * 8;
                    float v0 = acc[mt][nt][half * 2];
                    float v1 = acc[mt][nt][half * 2 + 1];
                    s1 += v0 * aSh[colh] + v1 * aSh[colh + 1];
                    s2 += v0 * aDh[colh] + v1 * aDh[colh + 1];
                }
                s1 += __shfl_xor_sync(0xffffffffu, s1, 1);
                s1 += __shfl_xor_sync(0xffffffffu, s1, 2);
                s2 += __shfl_xor_sync(0xffffffffu, s2, 1);
                s2 += __shfl_xor_sync(0xffffffffu, s2, 2);
                int r = rowBase + mt * 16 + half * 8;
                if ((lane & 3) == 0 && r < M) {
                    atomicAdd(&g_ssrc[r * Hh + head], s1);
                    atomicAdd(&g_sdst[r * Hh + head], s2);
                }
            }
        }
    }
}

// ---------------- CSR scan + self-loop fill: 2-barrier version ----------------
// 1024 threads, 10 elements each (thread-contiguous), warp-shuffle hierarchical scan.
__global__ void k_scanfill() {
    __shared__ int wsum[32];
    int tid = threadIdx.x;
    int lane = tid & 31, warp = tid >> 5;
    int base = tid * 10;
    int v[10];
    int run = 0;
#pragma unroll
    for (int i = 0; i < 10; i++) {
        int idx = base + i;
        int d = (idx < NN) ? (g_cnt[idx] + 1) : 0;   // +1 self loop
        run += d;
        v[i] = run;                                   // local inclusive prefix
    }
    int total = run;
    int inc = total;
#pragma unroll
    for (int o = 1; o < 32; o <<= 1) {
        int t = __shfl_up_sync(0xffffffffu, inc, o);
        if (lane >= o) inc += t;
    }
    if (lane == 31) wsum[warp] = inc;
    __syncthreads();
    if (warp == 0) {
        int w = wsum[lane];
        int winc = w;
#pragma unroll
        for (int o = 1; o < 32; o <<= 1) {
            int t = __shfl_up_sync(0xffffffffu, winc, o);
            if (lane >= o) winc += t;
        }
        wsum[lane] = winc - w;                        // exclusive warp offset
    }
    __syncthreads();
    int offset = wsum[warp] + (inc - total);          // exclusive prefix for this thread
    if (tid == 0) g_rowptr[0] = 0;
#pragma unroll
    for (int i = 0; i < 10; i++) {
        int idx = base + i;
        if (idx < NN) {
            int rp = offset + (i == 0 ? 0 : v[i - 1]);
            g_rowptr[idx + 1] = offset + v[i];
            g_csrc[rp] = idx;                         // self loop first
            g_cnt[idx] = rp + 1;                      // cursor for k_fill
        }
    }
}
__global__ void k_fill(const int* __restrict__ ei) {
    int e = blockIdx.x * blockDim.x + threadIdx.x;
    if (e < EE) {
        int dst = ei[EE + e];
        int slot = atomicAdd(&g_cnt[dst], 1);
        g_csrc[slot] = ei[e];
    }
}

__device__ __forceinline__ float lrelu02(float x) { return x > 0.f ? x : 0.2f * x; }

// ---------------- GAT aggregation, H=8, 8 nodes/block + inline BN partials ----------------
__global__ void k_agg8(const float* __restrict__ hbuf, const float* __restrict__ ssrc,
                       const float* __restrict__ sdst, const float* __restrict__ bias,
                       float* __restrict__ out) {
    int tid = threadIdx.x;
    int warp = tid >> 5, lane = tid & 31;
    int hh = tid >> 4;
    int c4 = (tid & 15) << 2;
    __shared__ float sh_sdst[HH], sh_m[HH], sh_sinv[HH];
    __shared__ float sh_alpha[32 * HH];
    __shared__ int   sh_src[32];
    float4 bb = *(const float4*)(bias + hh * CC + c4);
    float4 bsum = make_float4(0.f, 0.f, 0.f, 0.f);
    float4 bsq  = make_float4(0.f, 0.f, 0.f, 0.f);
    int base = blockIdx.x * ANB;

    for (int ni = 0; ni < ANB; ni++) {
        int dstn = base + ni;
        __syncthreads();
        if (tid < HH) sh_sdst[tid] = sdst[dstn * HH + tid];
        __syncthreads();
        int beg = g_rowptr[dstn], end = g_rowptr[dstn + 1];
        {
            int hh2 = warp * 2 + (lane >> 4);
            int sub = lane & 15;
            float sd = sh_sdst[hh2];
            float mx = -3.4e38f;
            for (int i = beg + sub; i < end; i += 16)
                mx = fmaxf(mx, lrelu02(ssrc[g_csrc[i] * HH + hh2] + sd));
#pragma unroll
            for (int o = 1; o < 16; o <<= 1) mx = fmaxf(mx, __shfl_xor_sync(0xffffffffu, mx, o));
            float se = 0.f;
            for (int i = beg + sub; i < end; i += 16)
                se += __expf(lrelu02(ssrc[g_csrc[i] * HH + hh2] + sd) - mx);
#pragma unroll
            for (int o = 1; o < 16; o <<= 1) se += __shfl_xor_sync(0xffffffffu, se, o);
            if (sub == 0) { sh_m[hh2] = mx; sh_sinv[hh2] = 1.f / (se + 1e-16f); }
        }
        __syncthreads();
        float4 acc = make_float4(0.f, 0.f, 0.f, 0.f);
        for (int c0 = beg; c0 < end; c0 += 32) {
            int cnt = min(32, end - c0);
            for (int t = tid; t < cnt * HH; t += 128) {
                int e = t >> 3, h2 = t & 7;
                int s = g_csrc[c0 + e];
                if (h2 == 0) sh_src[e] = s;
                sh_alpha[e * HH + h2] =
                    __expf(lrelu02(ssrc[s * HH + h2] + sh_sdst[h2]) - sh_m[h2]) * sh_sinv[h2];
            }
            __syncthreads();
            int e = 0;
            for (; e + 1 < cnt; e += 2) {
                float a0 = sh_alpha[e * HH + hh];
                float a1 = sh_alpha[(e + 1) * HH + hh];
                float4 v0 = *(const float4*)(hbuf + (size_t)sh_src[e] * HC + hh * CC + c4);
                float4 v1 = *(const float4*)(hbuf + (size_t)sh_src[e + 1] * HC + hh * CC + c4);
                acc.x = fmaf(a0, v0.x, fmaf(a1, v1.x, acc.x));
                acc.y = fmaf(a0, v0.y, fmaf(a1, v1.y, acc.y));
                acc.z = fmaf(a0, v0.z, fmaf(a1, v1.z, acc.z));
                acc.w = fmaf(a0, v0.w, fmaf(a1, v1.w, acc.w));
            }
            if (e < cnt) {
                float a0 = sh_alpha[e * HH + hh];
                float4 v0 = *(const float4*)(hbuf + (size_t)sh_src[e] * HC + hh * CC + c4);
                acc.x = fmaf(a0, v0.x, acc.x);
                acc.y = fmaf(a0, v0.y, acc.y);
                acc.z = fmaf(a0, v0.z, acc.z);
                acc.w = fmaf(a0, v0.w, acc.w);
            }
            __syncthreads();
        }
        float o0 = acc.x + bb.x, o1 = acc.y + bb.y;
        float o2 = acc.z + bb.z, o3 = acc.w + bb.w;
        *(float4*)(out + (size_t)dstn * HC + hh * CC + c4) = make_float4(o0, o1, o2, o3);
        bsum.x += o0; bsum.y += o1; bsum.z += o2; bsum.w += o3;
        bsq.x = fmaf(o0, o0, bsq.x); bsq.y = fmaf(o1, o1, bsq.y);
        bsq.z = fmaf(o2, o2, bsq.z); bsq.w = fmaf(o3, o3, bsq.w);
    }
    int bucket = blockIdx.x & (NBK - 1);
    float* p1 = g_bnpart  + bucket * HC + hh * CC + c4;
    float* p2 = g_bnpart2 + bucket * HC + hh * CC + c4;
    atomicAdd(p1 + 0, bsum.x); atomicAdd(p1 + 1, bsum.y);
    atomicAdd(p1 + 2, bsum.z); atomicAdd(p1 + 3, bsum.w);
    atomicAdd(p2 + 0, bsq.x);  atomicAdd(p2 + 1, bsq.y);
    atomicAdd(p2 + 2, bsq.z);  atomicAdd(p2 + 3, bsq.w);
}

// ---------------- GAT aggregation, H=1 C=64, 8 nodes/block + inline BN partials ----------------
__global__ void k_agg1(const float* __restrict__ h3, const float* __restrict__ ssrc,
                       const float* __restrict__ sdst, const float* __restrict__ bias,
                       float* __restrict__ out) {
    int tid = threadIdx.x;
    __shared__ float sh_m, sh_sinv;
    __shared__ float sh_alpha[64];
    __shared__ int   sh_src[64];
    float bbias = bias[tid];
    float bsum = 0.f, bsq = 0.f;
    int base = blockIdx.x * ANB;

    for (int ni = 0; ni < ANB; ni++) {
        int dstn = base + ni;
        float sd = sdst[dstn];
        int beg = g_rowptr[dstn], end = g_rowptr[dstn + 1];
        __syncthreads();
        if (tid < 32) {
            float mx = -3.4e38f;
            for (int i = beg + tid; i < end; i += 32)
                mx = fmaxf(mx, lrelu02(ssrc[g_csrc[i]] + sd));
#pragma unroll
            for (int o = 1; o < 32; o <<= 1) mx = fmaxf(mx, __shfl_xor_sync(0xffffffffu, mx, o));
            float se = 0.f;
            for (int i = beg + tid; i < end; i += 32)
                se += __expf(lrelu02(ssrc[g_csrc[i]] + sd) - mx);
#pragma unroll
            for (int o = 1; o < 32; o <<= 1) se += __shfl_xor_sync(0xffffffffu, se, o);
            if (tid == 0) { sh_m = mx; sh_sinv = 1.f / (se + 1e-16f); }
        }
        __syncthreads();
        float m = sh_m, sinv = sh_sinv;
        float acc = 0.f;
        for (int c0 = beg; c0 < end; c0 += 64) {
            int cnt = min(64, end - c0);
            if (tid < cnt) {
                int s = g_csrc[c0 + tid];
                sh_src[tid] = s;
                sh_alpha[tid] = __expf(lrelu02(ssrc[s] + sd) - m) * sinv;
            }
            __syncthreads();
            int e = 0;
            for (; e + 1 < cnt; e += 2) {
                float a0 = sh_alpha[e], a1 = sh_alpha[e + 1];
                float v0 = h3[(size_t)sh_src[e] * CC + tid];
                float v1 = h3[(size_t)sh_src[e + 1] * CC + tid];
                acc = fmaf(a0, v0, fmaf(a1, v1, acc));
            }
            if (e < cnt)
                acc = fmaf(sh_alpha[e], h3[(size_t)sh_src[e] * CC + tid], acc);
            __syncthreads();
        }
        float o = acc + bbias;
        out[(size_t)dstn * CC + tid] = o;
        bsum += o;
        bsq = fmaf(o, o, bsq);
    }
    int bucket = blockIdx.x & (NBK - 1);
    atomicAdd(&g_bnpart[bucket * CC + tid], bsum);
    atomicAdd(&g_bnpart2[bucket * CC + tid], bsq);
}

// ---------------- BN finalize (inline) + apply; optional bf16 split + score zeroing ----------------
__global__ void k_bnapply(const float* __restrict__ in, const float* __restrict__ res,
                          float* __restrict__ out,
                          __nv_bfloat16* __restrict__ outH, __nv_bfloat16* __restrict__ outL,
                          const float* __restrict__ g, const float* __restrict__ be,
                          int Cdim, int doElu, int total4, int zeroScores) {
    __shared__ float s_scale[HC], s_shift[HC];
    for (int c = threadIdx.x; c < Cdim; c += blockDim.x) {
        float ts = 0.f, tq = 0.f;
#pragma unroll
        for (int b = 0; b < NBK; b++) {
            ts += g_bnpart[b * Cdim + c];
            tq += g_bnpart2[b * Cdim + c];
        }
        float mu = ts / (float)NN;
        float var = tq / (float)NN - mu * mu;
        var = fmaxf(var, 0.f);
        float inv = rsqrtf(var + 1e-5f);
        float sc = g[c] * inv;
        s_scale[c] = sc;
        s_shift[c] = be[c] - sc * mu;
    }
    __syncthreads();

    int i0 = blockIdx.x * blockDim.x + threadIdx.x;
    int stride = gridDim.x * blockDim.x;
    if (zeroScores) {
        for (int zi = i0; zi < NN * HH; zi += stride) { g_ssrc[zi] = 0.f; g_sdst[zi] = 0.f; }
    }
    int c4cnt = Cdim >> 2;
    for (int i = i0; i < total4; i += stride) {
        int c4 = (i % c4cnt) << 2;
        float4 v = ((const float4*)in)[i];
        float4 sc = *(const float4*)&s_scale[c4];
        float4 sh = *(const float4*)&s_shift[c4];
        float o0 = fmaf(sc.x, v.x, sh.x);
        float o1 = fmaf(sc.y, v.y, sh.y);
        float o2 = fmaf(sc.z, v.z, sh.z);
        float o3 = fmaf(sc.w, v.w, sh.w);
        if (doElu) {
            o0 = o0 > 0.f ? o0 : expm1f(o0);
            o1 = o1 > 0.f ? o1 : expm1f(o1);
            o2 = o2 > 0.f ? o2 : expm1f(o2);
            o3 = o3 > 0.f ? o3 : expm1f(o3);
        }
        if (res) {
            float4 rv = ((const float4*)res)[i];
            o0 += rv.x; o1 += rv.y; o2 += rv.z; o3 += rv.w;
        }
        ((float4*)out)[i] = make_float4(o0, o1, o2, o3);
        if (outH) {
            __nv_bfloat16 h0, h1, h2, h3, l0, l1, l2, l3;
            split_bf16(o0, h0, l0); split_bf16(o1, h1, l1);
            split_bf16(o2, h2, l2); split_bf16(o3, h3, l3);
            ((__nv_bfloat162*)outH)[2 * i]     = __halves2bfloat162(h0, h1);
            ((__nv_bfloat162*)outH)[2 * i + 1] = __halves2bfloat162(h2, h3);
            ((__nv_bfloat162*)outL)[2 * i]     = __halves2bfloat162(l0, l1);
            ((__nv_bfloat162*)outL)[2 * i + 1] = __halves2bfloat162(l2, l3);
        }
    }
}

// ---------------- fused pool + classifier (batch is sorted) ----------------
__global__ void k_poolfinal(const float* __restrict__ x3, const int* __restrict__ batch,
                            const float* __restrict__ linW, const float* __restrict__ linb,
                            float* __restrict__ out) {
    int g = blockIdx.x;
    int j = threadIdx.x;
    __shared__ float xg[CC];
    int lo = 0, hi = NN;
    while (lo < hi) { int mid = (lo + hi) >> 1; if (batch[mid] < g) lo = mid + 1; else hi = mid; }
    int beg = lo;
    hi = NN;
    while (lo < hi) { int mid = (lo + hi) >> 1; if (batch[mid] <= g) lo = mid + 1; else hi = mid; }
    int end = lo;
    float s = 0.f;
    for (int n = beg; n < end; n++) s += x3[(size_t)n * CC + j];
    float cv = fmaxf((float)(end - beg), 1.0f);
    xg[j] = s / cv;
    __syncthreads();
    float acc = linb[j];
#pragma unroll
    for (int c = 0; c < CC; c++) acc = fmaf(xg[c], linW[c * NCLS + j], acc);
    out[g * NCLS + j] = acc;
}

// ---------------- host side ----------------
extern "C" void kernel_launch(void* const* d_in, const int* in_sizes, int n_in,
                              void* d_out, int out_size) {
    const float* x      = (const float*)d_in[0];
    const int*   ei     = (const int*)d_in[1];
    const int*   batch  = (const int*)d_in[2];
    const float* enc_W  = (const float*)d_in[3];
    const float* enc_b  = (const float*)d_in[4];
    const float* W1     = (const float*)d_in[5];
    const float* as1    = (const float*)d_in[6];
    const float* ad1    = (const float*)d_in[7];
    const float* b1     = (const float*)d_in[8];
    const float* g1     = (const float*)d_in[9];
    const float* be1    = (const float*)d_in[10];
    const float* W2     = (const float*)d_in[11];
    const float* as2    = (const float*)d_in[12];
    const float* ad2    = (const float*)d_in[13];
    const float* b2     = (const float*)d_in[14];
    const float* g2     = (const float*)d_in[15];
    const float* be2    = (const float*)d_in[16];
    const float* W3     = (const float*)d_in[17];
    const float* as3    = (const float*)d_in[18];
    const float* ad3    = (const float*)d_in[19];
    const float* b3     = (const float*)d_in[20];
    const float* g3     = (const float*)d_in[21];
    const float* be3    = (const float*)d_in[22];
    const float* linW   = (const float*)d_in[23];
    const float* linb   = (const float*)d_in[24];
    float* out = (float*)d_out;

    float *bufA, *bufB, *hbuf, *gat, *ssrc, *sdst, *x3, *gat3;
    int* cntp;
    __nv_bfloat16 *Ah, *Al, *Ah2, *Al2, *Wth, *Wtl;
    cudaGetSymbolAddress((void**)&bufA, g_bufA);
    cudaGetSymbolAddress((void**)&bufB, g_bufB);
    cudaGetSymbolAddress((void**)&hbuf, g_h);
    cudaGetSymbolAddress((void**)&gat,  g_gat);
    cudaGetSymbolAddress((void**)&ssrc, g_ssrc);
    cudaGetSymbolAddress((void**)&sdst, g_sdst);
    cudaGetSymbolAddress((void**)&x3,   g_x3);
    cudaGetSymbolAddress((void**)&gat3, g_gat3);
    cudaGetSymbolAddress((void**)&cntp, g_cnt);
    cudaGetSymbolAddress((void**)&Ah,   g_Ah);
    cudaGetSymbolAddress((void**)&Al,   g_Al);
    cudaGetSymbolAddress((void**)&Ah2,  g_Ah2);
    cudaGetSymbolAddress((void**)&Al2,  g_Al2);
    cudaGetSymbolAddress((void**)&Wth,  g_WthA);
    cudaGetSymbolAddress((void**)&Wtl,  g_WtlA);
    __nv_bfloat16 *Wth0 = Wth,              *Wtl0 = Wtl;
    __nv_bfloat16 *Wth1 = Wth + HC * HC,    *Wtl1 = Wtl + HC * HC;
    __nv_bfloat16 *Wth2 = Wth + 2 * HC * HC,*Wtl2 = Wtl + 2 * HC * HC;
    __nv_bfloat16 *Wth3 = Wth + 3 * HC * HC,*Wtl3 = Wtl + 3 * HC * HC;

    cudaFuncSetAttribute(k_gemm_mma, cudaFuncAttributeMaxDynamicSharedMemorySize, SMEM_GEMM);

    dim3 gGrid(HC / 64, (NN + 127) / 128);    // 8 x 79
    dim3 gGrid3(1, (NN + 127) / 128);         // 1 x 79
    const int T4 = NN * HC / 4;
    const int T4c = NN * CC / 4;
    const int AGB = NN / ANB;                 // 1250 aggregation blocks

    // zero degree counters via memset node (capturable, no allocation)
    cudaMemsetAsync(cntp, 0, NN * sizeof(int));
    // prep: weights + input split + zeroing + CSR degree count (one launch)
    k_prep<<<dim3(16, 16, 7), dim3(32, 8)>>>(x, Ah, Al, enc_W, W1, W2, W3, ei);
    // 2-barrier scan + self-loop fill
    k_scanfill<<<1, 1024>>>();
    // encoder GEMM
    k_gemm_mma<<<gGrid, 256, SMEM_GEMM>>>(Ah, Al, Wth0, Wtl0, enc_b, bufA, Ah2, Al2,
                                          nullptr, nullptr, HH, NN, HC);
    k_fill<<<(EE + 255) / 256, 256>>>(ei);

    // ---- layer 1 ----
    k_gemm_mma<<<gGrid, 256, SMEM_GEMM>>>(Ah2, Al2, Wth1, Wtl1, nullptr, hbuf, nullptr, nullptr,
                                          as1, ad1, HH, NN, HC);
    k_agg8<<<AGB, 128>>>(hbuf, ssrc, sdst, b1, gat);
    k_bnapply<<<512, 256>>>(gat, bufA, bufB, Ah, Al, g1, be1, HC, 1, T4, 1);

    // ---- layer 2 ----
    k_gemm_mma<<<gGrid, 256, SMEM_GEMM>>>(Ah, Al, Wth2, Wtl2, nullptr, hbuf, nullptr, nullptr,
                                          as2, ad2, HH, NN, HC);
    k_agg8<<<AGB, 128>>>(hbuf, ssrc, sdst, b2, gat);
    k_bnapply<<<512, 256>>>(gat, bufB, bufA, Ah2, Al2, g2, be2, HC, 1, T4, 1);

    // ---- layer 3 (H=1) ----
    k_gemm_mma<<<gGrid3, 256, SMEM_GEMM>>>(Ah2, Al2, Wth3, Wtl3, nullptr, x3, nullptr, nullptr,
                                           as3, ad3, 1, NN, CC);
    k_agg1<<<AGB, 64>>>(x3, ssrc, sdst, b3, gat3);
    k_bnapply<<<256, 256>>>(gat3, nullptr, x3, nullptr, nullptr, g3, be3, CC, 0, T4c, 0);

    // ---- fused pool + classifier ----
    k_poolfinal<<<GG, NCLS>>>(x3, batch, linW, linb, out);
}